// round 12
// baseline (speedup 1.0000x reference)
#include <cuda_runtime.h>
#include <cuda_fp16.h>
#include <cstdint>

#define S 2048
#define D 64
#define NB 2
#define HH 8
#define NH 16
#define SW 64                      /* S/32 mask words per row */
#define CTX_ELEMS (NB*HH*S*D)

// ---------------- scratch (__device__ globals; no allocations) --------------
__device__ __half    g_Qh[NB*HH*S*D];   // softmaxed Q, fp16
__device__ __half    g_Kh[NB*HH*S*D];   // softmaxed K, fp16
__device__ __half    g_Vf[NB*HH*S*D];   // V, fp16
__device__ unsigned  g_mb[S*SW];        // packed mask bits
// unnormalized masked exp(logits), fp16, thread-linear fragment layout:
// idx = ((((cta*8 + wid)*16 + kt)*4 + c)*4 + f4)*32 + lid   (uint2 each)
__device__ uint2     g_e[(size_t)256*8*16*4*4*32];   // 134 MB

#define SWZ(o) ((o) ^ (((o) >> 3) & 0x70))

__device__ __forceinline__ uint32_t smem_u32(const void* p) {
    uint32_t a;
    asm("{ .reg .u64 t; cvta.to.shared.u64 t, %1; cvt.u32.u64 %0, t; }" : "=r"(a) : "l"(p));
    return a;
}
__device__ __forceinline__ void cpa16(uint32_t dst, const void* src) {
    asm volatile("cp.async.cg.shared.global [%0], [%1], 16;"
                 :: "r"(dst), "l"(__cvta_generic_to_global(src)) : "memory");
}
#define CPA_COMMIT() asm volatile("cp.async.commit_group;" ::: "memory")
#define CPA_WAIT0()  asm volatile("cp.async.wait_group 0;" ::: "memory")

__device__ __forceinline__ void ldsm4(uint32_t* r, uint32_t a) {
    asm volatile("ldmatrix.sync.aligned.m8n8.x4.shared.b16 {%0,%1,%2,%3}, [%4];"
                 : "=r"(r[0]), "=r"(r[1]), "=r"(r[2]), "=r"(r[3]) : "r"(a));
}
__device__ __forceinline__ void ldsm4t(uint32_t* r, uint32_t a) {
    asm volatile("ldmatrix.sync.aligned.m8n8.x4.trans.shared.b16 {%0,%1,%2,%3}, [%4];"
                 : "=r"(r[0]), "=r"(r[1]), "=r"(r[2]), "=r"(r[3]) : "r"(a));
}
__device__ __forceinline__ void mma_fp(float* c, const uint32_t* a, const uint32_t* b) {
    asm volatile("mma.sync.aligned.m16n8k16.row.col.f32.f16.f16.f32 "
                 "{%0,%1,%2,%3}, {%4,%5,%6,%7}, {%8,%9}, {%0,%1,%2,%3};"
                 : "+f"(c[0]), "+f"(c[1]), "+f"(c[2]), "+f"(c[3])
                 : "r"(a[0]), "r"(a[1]), "r"(a[2]), "r"(a[3]), "r"(b[0]), "r"(b[1]));
}

// ---------------------------------------------------------------------------
// softmax over axis=2 (sequence) for Q -> fp16
// ---------------------------------------------------------------------------
__global__ void k_softmax_q(const float* __restrict__ q) {
    int nh = blockIdx.x, dchunk = blockIdx.y;
    int dloc = threadIdx.x & 7, sy = threadIdx.x >> 3;
    int d = dchunk * 8 + dloc;
    const float* base = q + (size_t)nh * S * D + d;
    float sum = 0.f;
    for (int s = sy; s < S; s += 32) sum += __expf(base[(size_t)s * D]);
    __shared__ float red[32][8];
    red[sy][dloc] = sum;
    __syncthreads();
    for (int off = 16; off > 0; off >>= 1) {
        if (sy < off) red[sy][dloc] += red[sy + off][dloc];
        __syncthreads();
    }
    float iv = 1.f / red[0][dloc];
    __half* out = g_Qh + (size_t)nh * S * D + d;
    for (int s = sy; s < S; s += 32)
        out[(size_t)s * D] = __float2half_rn(__expf(base[(size_t)s * D]) * iv);
}

// ---------------------------------------------------------------------------
// softmax over axis=1 (heads) for K -> fp16
// ---------------------------------------------------------------------------
__global__ void k_softmax_k(const float* __restrict__ k) {
    int idx = blockIdx.x * blockDim.x + threadIdx.x;
    if (idx >= NB * S * D) return;
    int n = idx / (S * D);
    int sd = idx - n * (S * D);
    const float* p = k + (size_t)n * HH * S * D + sd;
    __half* o = g_Kh + (size_t)n * HH * S * D + sd;
    float e[HH]; float sum = 0.f;
#pragma unroll
    for (int h = 0; h < HH; h++) { e[h] = __expf(p[(size_t)h * S * D]); sum += e[h]; }
    float iv = 1.f / sum;
#pragma unroll
    for (int h = 0; h < HH; h++) o[(size_t)h * S * D] = __float2half_rn(e[h] * iv);
}

// ---------------------------------------------------------------------------
// pack mask bits
// ---------------------------------------------------------------------------
__global__ void k_pack_mask(const int* __restrict__ m) {
    int idx = blockIdx.x * blockDim.x + threadIdx.x;
    if (idx >= S * SW) return;
    int qq = idx >> 6, w = idx & 63;
    const int* p = m + (size_t)qq * S + w * 32;
    unsigned bits = 0;
#pragma unroll
    for (int b = 0; b < 32; b++) if (p[b] != 0) bits |= (1u << b);
    g_mb[idx] = bits;
}

// ---------------------------------------------------------------------------
// V convert: g_Vf = fp16(V)
// ---------------------------------------------------------------------------
__global__ void k_vhalf(const float* __restrict__ v) {
    int idx = blockIdx.x * blockDim.x + threadIdx.x;   // over quads
    if (idx >= NB * HH * S * D / 4) return;
    float4 f = *(const float4*)(v + (size_t)idx * 4);
    __half2 h01 = __floats2half2_rn(f.x, f.y);
    __half2 h23 = __floats2half2_rn(f.z, f.w);
    *(uint2*)(g_Vf + (size_t)idx * 4) = make_uint2(*(uint32_t*)&h01, *(uint32_t*)&h23);
}

// ---------------------------------------------------------------------------
// fused attention:
//   pass1: GEMM1 (fp16 HMMA) + masked exp -> row sums; e (fp16) -> g_e
//   pass2: read e, normalize (fp32), store attn fp32, GEMM2 (fp16) -> ctx
// ---------------------------------------------------------------------------
#define O_INVL 0
#define O_MB0  512
#define O_MB1  2560
#define O_KB0  4608
#define O_KB1  20992    /* also Q tile during prologue */
#define O_VH0  37376
#define O_VH1  53760
#define SMEM_T 70144

__global__ void __launch_bounds__(256, 2) k_attn(float* __restrict__ attn,
                                                 float* __restrict__ ctx) {
    extern __shared__ char smem[];
    const int tid = threadIdx.x, wid = tid >> 5, lid = tid & 31;
    const int g = lid >> 2, t = lid & 3;
    const int nh = blockIdx.y, q0 = blockIdx.x * 128;
    const int cta = blockIdx.y * 16 + blockIdx.x;
    const uint32_t sb = smem_u32(smem);
    float* invl = (float*)(smem + O_INVL);

    const __half* Qg = g_Qh + ((size_t)nh * S + q0) * D;
    const __half* Kg = g_Kh + (size_t)nh * S * D;
    const __half* Vg = g_Vf + (size_t)nh * S * D;
    float* attnb = attn + (size_t)nh * S * S;
    uint2* eW = g_e + ((size_t)(cta * 8 + wid) * 16) * 512 + lid;

    // ---- prefetch K tile 0 + mask 0 into buf 0 (overlaps Q load/hoist) ----
    {
#pragma unroll
        for (int i = 0; i < 4; i++) {
            int idx = i * 256 + tid;
            int r = idx >> 3, s16 = idx & 7;
            cpa16(sb + O_KB0 + SWZ(r * 128 + s16 * 16), Kg + (size_t)r * 64 + s16 * 8);
        }
        if (tid < 128)
            cpa16(sb + O_MB0 + tid * 16, g_mb + (size_t)(q0 + tid) * SW);
        CPA_COMMIT();
    }

    // ---- load Q tile into KB1 region, hoist fragments, then recycle ----
#pragma unroll
    for (int i = 0; i < 4; i++) {
        int idx = i * 256 + tid;
        int r = idx >> 3, s16 = idx & 7;
        *(uint4*)(smem + O_KB1 + SWZ(r * 128 + s16 * 16)) =
            *(const uint4*)(Qg + (size_t)r * 64 + s16 * 8);
    }
    __syncthreads();
    uint32_t aQ[4][4];
#pragma unroll
    for (int kk = 0; kk < 4; kk++) {
        int rl = 16 * wid + (lid & 7) + (lid & 8);
        int c16 = kk * 2 + (lid >> 4);
        ldsm4(aQ[kk], sb + O_KB1 + SWZ(rl * 128 + c16 * 16));
    }
    __syncthreads();   // Q region now reusable as K buffer 1

    const int r0l = 16 * wid + g, r1l = r0l + 8;

    // ================= pass 1: GEMM1 + masked exp -> e, row sums ============
    float rs0 = 0.f, rs1 = 0.f;
    for (int kt = 0; kt < 16; kt++) {
        CPA_WAIT0();
        __syncthreads();
        if (kt < 15) {   // prefetch kt+1
            int b = (kt + 1) & 1;
            uint32_t kb = b ? O_KB1 : O_KB0, mb = b ? O_MB1 : O_MB0;
#pragma unroll
            for (int i = 0; i < 4; i++) {
                int idx = i * 256 + tid;
                int r = idx >> 3, s16 = idx & 7;
                cpa16(sb + kb + SWZ(r * 128 + s16 * 16),
                      Kg + (size_t)((kt + 1) * 128 + r) * 64 + s16 * 8);
            }
            if (tid < 128)
                cpa16(sb + mb + tid * 16, g_mb + (size_t)(q0 + tid) * SW + (kt + 1) * 4);
            CPA_COMMIT();
        }
        const uint32_t kb = (kt & 1) ? O_KB1 : O_KB0;
        const uint32_t mb = (kt & 1) ? O_MB1 : O_MB0;

        uint4 mw0 = *(uint4*)(smem + mb + r0l * 16);
        uint4 mw1 = *(uint4*)(smem + mb + r1l * 16);
        unsigned m0a[4] = {mw0.x, mw0.y, mw0.z, mw0.w};
        unsigned m1a[4] = {mw1.x, mw1.y, mw1.z, mw1.w};
        uint2* eT = eW + kt * 512;

#pragma unroll
        for (int c = 0; c < 4; c++) {
            float acc4[4][4];
#pragma unroll
            for (int f4 = 0; f4 < 4; f4++) { acc4[f4][0] = acc4[f4][1] = acc4[f4][2] = acc4[f4][3] = 0.f; }
#pragma unroll
            for (int f4 = 0; f4 < 4; f4++) {
                int f = 4 * c + f4;
#pragma unroll
                for (int kp = 0; kp < 2; kp++) {
                    uint32_t b[4];
                    ldsm4(b, sb + kb + SWZ((f * 8 + (lid & 7)) * 128 + (kp * 4 + (lid >> 3)) * 16));
                    mma_fp(acc4[f4], aQ[2 * kp], b);
                    mma_fp(acc4[f4], aQ[2 * kp + 1], b + 2);
                }
            }
            unsigned w0 = m0a[c], w1 = m1a[c];
#pragma unroll
            for (int f4 = 0; f4 < 4; f4++) {
                int bit = 8 * f4 + 2 * t;
                float e0 = ((w0 >> bit) & 1)       ? __expf(acc4[f4][0]) : 0.f;
                float e1 = ((w0 >> (bit + 1)) & 1) ? __expf(acc4[f4][1]) : 0.f;
                float e2 = ((w1 >> bit) & 1)       ? __expf(acc4[f4][2]) : 0.f;
                float e3 = ((w1 >> (bit + 1)) & 1) ? __expf(acc4[f4][3]) : 0.f;
                rs0 += e0 + e1;
                rs1 += e2 + e3;
                __half2 p01 = __floats2half2_rn(e0, e1);
                __half2 p23 = __floats2half2_rn(e2, e3);
                eT[(c * 4 + f4) * 32] = make_uint2(*(uint32_t*)&p01, *(uint32_t*)&p23);
            }
        }
    }

    // ---- prefetch pass-2 V tile 0 early (overlaps reduction) ----
    {
#pragma unroll
        for (int i = 0; i < 4; i++) {
            int idx = i * 256 + tid;
            int r = idx >> 3, s16 = idx & 7;
            cpa16(sb + O_VH0 + SWZ(r * 128 + s16 * 16), Vg + (size_t)r * 64 + s16 * 8);
        }
        CPA_COMMIT();
    }

    rs0 += __shfl_xor_sync(0xffffffffu, rs0, 1);
    rs0 += __shfl_xor_sync(0xffffffffu, rs0, 2);
    rs1 += __shfl_xor_sync(0xffffffffu, rs1, 1);
    rs1 += __shfl_xor_sync(0xffffffffu, rs1, 2);
    if (t == 0) {
        invl[r0l] = rs0 > 0.f ? 1.f / rs0 : 0.f;
        invl[r1l] = rs1 > 0.f ? 1.f / rs1 : 0.f;
    }
    __syncthreads();
    const float iv0 = invl[r0l], iv1 = invl[r1l];

    // ================= pass 2: normalize e + attn store + GEMM2 =============
    float ctxa[8][4];
#pragma unroll
    for (int n = 0; n < 8; n++) { ctxa[n][0] = ctxa[n][1] = ctxa[n][2] = ctxa[n][3] = 0.f; }

    for (int kt = 0; kt < 16; kt++) {
        CPA_WAIT0();
        __syncthreads();
        if (kt < 15) {   // prefetch V kt+1
            uint32_t vh = ((kt + 1) & 1) ? O_VH1 : O_VH0;
#pragma unroll
            for (int i = 0; i < 4; i++) {
                int idx = i * 256 + tid;
                int r = idx >> 3, s16 = idx & 7;
                cpa16(sb + vh + SWZ(r * 128 + s16 * 16),
                      Vg + (size_t)((kt + 1) * 128 + r) * 64 + s16 * 8);
            }
            CPA_COMMIT();
        }
        const uint32_t vhb = (kt & 1) ? O_VH1 : O_VH0;
        uint2* eT = eW + kt * 512;

#pragma unroll
        for (int c = 0; c < 4; c++) {
            // --- read e, normalize fp32, store attn, repack fp16 W frags ---
            uint32_t wv[4][2];
#pragma unroll
            for (int f4 = 0; f4 < 4; f4++) {
                uint2 ee = eT[(c * 4 + f4) * 32];
                float2 f01 = __half22float2(*(__half2*)&ee.x);
                float2 f23 = __half22float2(*(__half2*)&ee.y);
                f01.x *= iv0; f01.y *= iv0;
                f23.x *= iv1; f23.y *= iv1;
                int col = kt * 128 + 32 * c + 8 * f4 + 2 * t;
                *(float2*)&attnb[(size_t)(q0 + r0l) * S + col] = f01;
                *(float2*)&attnb[(size_t)(q0 + r1l) * S + col] = f23;
                __half2 h01 = __floats2half2_rn(f01.x, f01.y);
                __half2 h23 = __floats2half2_rn(f23.x, f23.y);
                wv[f4][0] = *(uint32_t*)&h01;
                wv[f4][1] = *(uint32_t*)&h23;
            }
            // --- GEMM2 partial: ctx += W[:,32c..32c+31] @ V[32c..32c+31,:] ---
            uint32_t aH0[4] = {wv[0][0], wv[0][1], wv[1][0], wv[1][1]};
            uint32_t aH1[4] = {wv[2][0], wv[2][1], wv[3][0], wv[3][1]};
#pragma unroll
            for (int n8 = 0; n8 < 8; n8++) {
                uint32_t bh[4];
                ldsm4t(bh, sb + vhb + SWZ((c * 32 + lid) * 128 + n8 * 16));
                mma_fp(ctxa[n8], aH0, bh);
                mma_fp(ctxa[n8], aH1, bh + 2);
            }
        }
    }

    // ---- ctx store ----
#pragma unroll
    for (int n8 = 0; n8 < 8; n8++) {
        int c = 8 * n8 + 2 * t;
        *(float2*)&ctx[((size_t)nh * S + q0 + r0l) * D + c] = make_float2(ctxa[n8][0], ctxa[n8][1]);
        *(float2*)&ctx[((size_t)nh * S + q0 + r1l) * D + c] = make_float2(ctxa[n8][2], ctxa[n8][3]);
    }
}

// ---------------------------------------------------------------------------
extern "C" void kernel_launch(void* const* d_in, const int* in_sizes, int n_in,
                              void* d_out, int out_size) {
    const float* q = (const float*)d_in[0];
    const float* k = (const float*)d_in[1];
    const float* v = (const float*)d_in[2];
    const int*   m = (const int*)d_in[3];

    float* ctx  = (float*)d_out;
    float* attn = (float*)d_out + CTX_ELEMS;

    cudaFuncSetAttribute(k_attn, cudaFuncAttributeMaxDynamicSharedMemorySize, SMEM_T);

    k_softmax_q<<<dim3(NH, 8), 256>>>(q);
    k_softmax_k<<<(NB * S * D + 255) / 256, 256>>>(k);
    k_pack_mask<<<(S * SW + 255) / 256, 256>>>(m);
    k_vhalf<<<(NB * HH * S * D / 4 + 255) / 256, 256>>>(v);
    k_attn<<<dim3(16, NH), 256, SMEM_T>>>(attn, ctx);
}

// round 13
// speedup vs baseline: 1.9885x; 1.9885x over previous
#include <cuda_runtime.h>
#include <cuda_fp16.h>
#include <cstdint>

#define S 2048
#define D 64
#define NB 2
#define HH 8
#define NH 16
#define SW 64                      /* S/32 mask words per row */
#define CTX_ELEMS (NB*HH*S*D)

// ---------------- scratch (__device__ globals; no allocations) --------------
__device__ __half    g_Qh[NB*HH*S*D];   // softmaxed Q, fp16
__device__ __half    g_Kh[NB*HH*S*D];   // softmaxed K, fp16
__device__ __half    g_Vf[NB*HH*S*D];   // V, fp16
__device__ unsigned  g_mb[S*SW];        // packed mask bits

#define SWZ(o) ((o) ^ (((o) >> 3) & 0x70))

__device__ __forceinline__ uint32_t smem_u32(const void* p) {
    uint32_t a;
    asm("{ .reg .u64 t; cvta.to.shared.u64 t, %1; cvt.u32.u64 %0, t; }" : "=r"(a) : "l"(p));
    return a;
}
__device__ __forceinline__ void cpa16(uint32_t dst, const void* src) {
    asm volatile("cp.async.cg.shared.global [%0], [%1], 16;"
                 :: "r"(dst), "l"(__cvta_generic_to_global(src)) : "memory");
}
#define CPA_COMMIT() asm volatile("cp.async.commit_group;" ::: "memory")
#define CPA_WAIT0()  asm volatile("cp.async.wait_group 0;" ::: "memory")

__device__ __forceinline__ void ldsm4(uint32_t* r, uint32_t a) {
    asm volatile("ldmatrix.sync.aligned.m8n8.x4.shared.b16 {%0,%1,%2,%3}, [%4];"
                 : "=r"(r[0]), "=r"(r[1]), "=r"(r[2]), "=r"(r[3]) : "r"(a));
}
__device__ __forceinline__ void ldsm4t(uint32_t* r, uint32_t a) {
    asm volatile("ldmatrix.sync.aligned.m8n8.x4.trans.shared.b16 {%0,%1,%2,%3}, [%4];"
                 : "=r"(r[0]), "=r"(r[1]), "=r"(r[2]), "=r"(r[3]) : "r"(a));
}
__device__ __forceinline__ void mma_fp(float* c, const uint32_t* a, const uint32_t* b) {
    asm volatile("mma.sync.aligned.m16n8k16.row.col.f32.f16.f16.f32 "
                 "{%0,%1,%2,%3}, {%4,%5,%6,%7}, {%8,%9}, {%0,%1,%2,%3};"
                 : "+f"(c[0]), "+f"(c[1]), "+f"(c[2]), "+f"(c[3])
                 : "r"(a[0]), "r"(a[1]), "r"(a[2]), "r"(a[3]), "r"(b[0]), "r"(b[1]));
}
__device__ __forceinline__ void stg_cs_f2(float* p, float2 v) {
    asm volatile("st.global.cs.v2.f32 [%0], {%1, %2};"
                 :: "l"(__cvta_generic_to_global(p)), "f"(v.x), "f"(v.y) : "memory");
}

// ---------------------------------------------------------------------------
// softmax over axis=2 (sequence) for Q -> fp16
// ---------------------------------------------------------------------------
__global__ void k_softmax_q(const float* __restrict__ q) {
    int nh = blockIdx.x, dchunk = blockIdx.y;
    int dloc = threadIdx.x & 7, sy = threadIdx.x >> 3;
    int d = dchunk * 8 + dloc;
    const float* base = q + (size_t)nh * S * D + d;
    float sum = 0.f;
    for (int s = sy; s < S; s += 32) sum += __expf(base[(size_t)s * D]);
    __shared__ float red[32][8];
    red[sy][dloc] = sum;
    __syncthreads();
    for (int off = 16; off > 0; off >>= 1) {
        if (sy < off) red[sy][dloc] += red[sy + off][dloc];
        __syncthreads();
    }
    float iv = 1.f / red[0][dloc];
    __half* out = g_Qh + (size_t)nh * S * D + d;
    for (int s = sy; s < S; s += 32)
        out[(size_t)s * D] = __float2half_rn(__expf(base[(size_t)s * D]) * iv);
}

// ---------------------------------------------------------------------------
// softmax over axis=1 (heads) for K -> fp16
// ---------------------------------------------------------------------------
__global__ void k_softmax_k(const float* __restrict__ k) {
    int idx = blockIdx.x * blockDim.x + threadIdx.x;
    if (idx >= NB * S * D) return;
    int n = idx / (S * D);
    int sd = idx - n * (S * D);
    const float* p = k + (size_t)n * HH * S * D + sd;
    __half* o = g_Kh + (size_t)n * HH * S * D + sd;
    float e[HH]; float sum = 0.f;
#pragma unroll
    for (int h = 0; h < HH; h++) { e[h] = __expf(p[(size_t)h * S * D]); sum += e[h]; }
    float iv = 1.f / sum;
#pragma unroll
    for (int h = 0; h < HH; h++) o[(size_t)h * S * D] = __float2half_rn(e[h] * iv);
}

// ---------------------------------------------------------------------------
// pack mask bits
// ---------------------------------------------------------------------------
__global__ void k_pack_mask(const int* __restrict__ m) {
    int idx = blockIdx.x * blockDim.x + threadIdx.x;
    if (idx >= S * SW) return;
    int qq = idx >> 6, w = idx & 63;
    const int* p = m + (size_t)qq * S + w * 32;
    unsigned bits = 0;
#pragma unroll
    for (int b = 0; b < 32; b++) if (p[b] != 0) bits |= (1u << b);
    g_mb[idx] = bits;
}

// ---------------------------------------------------------------------------
// V convert: g_Vf = fp16(V)
// ---------------------------------------------------------------------------
__global__ void k_vhalf(const float* __restrict__ v) {
    int idx = blockIdx.x * blockDim.x + threadIdx.x;   // over quads
    if (idx >= NB * HH * S * D / 4) return;
    float4 f = *(const float4*)(v + (size_t)idx * 4);
    __half2 h01 = __floats2half2_rn(f.x, f.y);
    __half2 h23 = __floats2half2_rn(f.z, f.w);
    *(uint2*)(g_Vf + (size_t)idx * 4) = make_uint2(*(uint32_t*)&h01, *(uint32_t*)&h23);
}

// ---------------------------------------------------------------------------
// fused attention, cp.async double-buffered, fp16 MMA path
//   pass1: GEMM1 (software-pipelined B-LDSM) + masked exp -> row sums
//   pass2: GEMM1 again, normalize, stream attn fp32 (.cs), GEMM2 -> ctx
// ---------------------------------------------------------------------------
#define O_INVL 0
#define O_MB0  512
#define O_MB1  2560
#define O_KB0  4608
#define O_KB1  20992    /* also Q tile during prologue */
#define O_VH0  37376
#define O_VH1  53760
#define SMEM_T 70144

__global__ void __launch_bounds__(256, 2) k_attn(float* __restrict__ attn,
                                                 float* __restrict__ ctx) {
    extern __shared__ char smem[];
    const int tid = threadIdx.x, wid = tid >> 5, lid = tid & 31;
    const int g = lid >> 2, t = lid & 3;
    const int nh = blockIdx.y, q0 = blockIdx.x * 128;
    const uint32_t sb = smem_u32(smem);
    float* invl = (float*)(smem + O_INVL);

    const __half* Qg = g_Qh + ((size_t)nh * S + q0) * D;
    const __half* Kg = g_Kh + (size_t)nh * S * D;
    const __half* Vg = g_Vf + (size_t)nh * S * D;
    float* attnb = attn + (size_t)nh * S * S;

    // ---- prefetch K tile 0 + mask 0 into buf 0 (overlaps Q load/hoist) ----
    {
#pragma unroll
        for (int i = 0; i < 4; i++) {
            int idx = i * 256 + tid;
            int r = idx >> 3, s16 = idx & 7;
            cpa16(sb + O_KB0 + SWZ(r * 128 + s16 * 16), Kg + (size_t)r * 64 + s16 * 8);
        }
        if (tid < 128)
            cpa16(sb + O_MB0 + tid * 16, g_mb + (size_t)(q0 + tid) * SW);
        CPA_COMMIT();
    }

    // ---- load Q tile into KB1 region, hoist fragments, then recycle ----
#pragma unroll
    for (int i = 0; i < 4; i++) {
        int idx = i * 256 + tid;
        int r = idx >> 3, s16 = idx & 7;
        *(uint4*)(smem + O_KB1 + SWZ(r * 128 + s16 * 16)) =
            *(const uint4*)(Qg + (size_t)r * 64 + s16 * 8);
    }
    __syncthreads();
    uint32_t aQ[4][4];
#pragma unroll
    for (int kk = 0; kk < 4; kk++) {
        int rl = 16 * wid + (lid & 7) + (lid & 8);
        int c16 = kk * 2 + (lid >> 4);
        ldsm4(aQ[kk], sb + O_KB1 + SWZ(rl * 128 + c16 * 16));
    }
    __syncthreads();   // Q region now reusable as K buffer 1

    const int r0l = 16 * wid + g, r1l = r0l + 8;

    // ================= pass 1: row sums (pipelined B-LDSM) =================
    float rs0 = 0.f, rs1 = 0.f;
    for (int kt = 0; kt < 16; kt++) {
        CPA_WAIT0();
        __syncthreads();
        if (kt < 15) {   // prefetch kt+1
            int b = (kt + 1) & 1;
            uint32_t kb = b ? O_KB1 : O_KB0, mb = b ? O_MB1 : O_MB0;
#pragma unroll
            for (int i = 0; i < 4; i++) {
                int idx = i * 256 + tid;
                int r = idx >> 3, s16 = idx & 7;
                cpa16(sb + kb + SWZ(r * 128 + s16 * 16),
                      Kg + (size_t)((kt + 1) * 128 + r) * 64 + s16 * 8);
            }
            if (tid < 128)
                cpa16(sb + mb + tid * 16, g_mb + (size_t)(q0 + tid) * SW + (kt + 1) * 4);
            CPA_COMMIT();
        }
        const uint32_t kb = (kt & 1) ? O_KB1 : O_KB0;
        const uint32_t mb = (kt & 1) ? O_MB1 : O_MB0;

        uint4 mw0 = *(uint4*)(smem + mb + r0l * 16);
        uint4 mw1 = *(uint4*)(smem + mb + r1l * 16);
        unsigned m0a[4] = {mw0.x, mw0.y, mw0.z, mw0.w};
        unsigned m1a[4] = {mw1.x, mw1.y, mw1.z, mw1.w};

        // flat fragment loop with one-step B lookahead
        float acc4[4][4];
        uint32_t bn[8], bc[8];
        ldsm4(bn,     sb + kb + SWZ((0 * 8 + (lid & 7)) * 128 + (0 * 4 + (lid >> 3)) * 16));
        ldsm4(bn + 4, sb + kb + SWZ((0 * 8 + (lid & 7)) * 128 + (1 * 4 + (lid >> 3)) * 16));
#pragma unroll
        for (int f = 0; f < 16; f++) {
            const int f4 = f & 3;
#pragma unroll
            for (int j = 0; j < 8; j++) bc[j] = bn[j];
            if (f < 15) {
                ldsm4(bn,     sb + kb + SWZ(((f + 1) * 8 + (lid & 7)) * 128 + (0 * 4 + (lid >> 3)) * 16));
                ldsm4(bn + 4, sb + kb + SWZ(((f + 1) * 8 + (lid & 7)) * 128 + (1 * 4 + (lid >> 3)) * 16));
            }
            acc4[f4][0] = acc4[f4][1] = acc4[f4][2] = acc4[f4][3] = 0.f;
            mma_fp(acc4[f4], aQ[0], bc);
            mma_fp(acc4[f4], aQ[1], bc + 2);
            mma_fp(acc4[f4], aQ[2], bc + 4);
            mma_fp(acc4[f4], aQ[3], bc + 6);
            if (f4 == 3) {
                const int c = f >> 2;
                unsigned w0 = m0a[c], w1 = m1a[c];
#pragma unroll
                for (int u = 0; u < 4; u++) {
                    int bit = 8 * u + 2 * t;
                    if ((w0 >> bit) & 1)       rs0 += __expf(acc4[u][0]);
                    if ((w0 >> (bit + 1)) & 1) rs0 += __expf(acc4[u][1]);
                    if ((w1 >> bit) & 1)       rs1 += __expf(acc4[u][2]);
                    if ((w1 >> (bit + 1)) & 1) rs1 += __expf(acc4[u][3]);
                }
            }
        }
    }

    // ---- prefetch pass-2 tile 0 early (overlaps reduction) ----
    {
#pragma unroll
        for (int i = 0; i < 4; i++) {
            int idx = i * 256 + tid;
            int r = idx >> 3, s16 = idx & 7;
            uint32_t swo = SWZ(r * 128 + s16 * 16);
            size_t gofs = (size_t)r * 64 + s16 * 8;
            cpa16(sb + O_KB0 + swo, Kg + gofs);
            cpa16(sb + O_VH0 + swo, Vg + gofs);
        }
        if (tid < 128)
            cpa16(sb + O_MB0 + tid * 16, g_mb + (size_t)(q0 + tid) * SW);
        CPA_COMMIT();
    }

    rs0 += __shfl_xor_sync(0xffffffffu, rs0, 1);
    rs0 += __shfl_xor_sync(0xffffffffu, rs0, 2);
    rs1 += __shfl_xor_sync(0xffffffffu, rs1, 1);
    rs1 += __shfl_xor_sync(0xffffffffu, rs1, 2);
    if (t == 0) {
        invl[r0l] = rs0 > 0.f ? 1.f / rs0 : 0.f;
        invl[r1l] = rs1 > 0.f ? 1.f / rs1 : 0.f;
    }
    __syncthreads();
    const float iv0 = invl[r0l], iv1 = invl[r1l];

    // ================= pass 2: recompute + normalize + chunked GEMM2 ========
    float ctxa[8][4];
#pragma unroll
    for (int n = 0; n < 8; n++) { ctxa[n][0] = ctxa[n][1] = ctxa[n][2] = ctxa[n][3] = 0.f; }

    for (int kt = 0; kt < 16; kt++) {
        CPA_WAIT0();
        __syncthreads();
        if (kt < 15) {   // prefetch kt+1
            int b = (kt + 1) & 1;
            uint32_t kb = b ? O_KB1 : O_KB0, vh = b ? O_VH1 : O_VH0;
            uint32_t mb = b ? O_MB1 : O_MB0;
#pragma unroll
            for (int i = 0; i < 4; i++) {
                int idx = i * 256 + tid;
                int r = idx >> 3, s16 = idx & 7;
                uint32_t swo = SWZ(r * 128 + s16 * 16);
                size_t gofs = (size_t)((kt + 1) * 128 + r) * 64 + s16 * 8;
                cpa16(sb + kb + swo, Kg + gofs);
                cpa16(sb + vh + swo, Vg + gofs);
            }
            if (tid < 128)
                cpa16(sb + mb + tid * 16, g_mb + (size_t)(q0 + tid) * SW + (kt + 1) * 4);
            CPA_COMMIT();
        }
        const int bsel = kt & 1;
        const uint32_t kb  = bsel ? O_KB1 : O_KB0;
        const uint32_t vhb = bsel ? O_VH1 : O_VH0;
        const uint32_t mb  = bsel ? O_MB1 : O_MB0;

        uint4 mw0 = *(uint4*)(smem + mb + r0l * 16);
        uint4 mw1 = *(uint4*)(smem + mb + r1l * 16);
        unsigned m0a[4] = {mw0.x, mw0.y, mw0.z, mw0.w};
        unsigned m1a[4] = {mw1.x, mw1.y, mw1.z, mw1.w};

#pragma unroll
        for (int c = 0; c < 4; c++) {
            // --- GEMM1 for 4 fragments (32 attn cols) ---
            float acc4[4][4];
#pragma unroll
            for (int f4 = 0; f4 < 4; f4++) { acc4[f4][0] = acc4[f4][1] = acc4[f4][2] = acc4[f4][3] = 0.f; }
#pragma unroll
            for (int f4 = 0; f4 < 4; f4++) {
                int f = 4 * c + f4;
#pragma unroll
                for (int kp = 0; kp < 2; kp++) {
                    uint32_t b[4];
                    ldsm4(b, sb + kb + SWZ((f * 8 + (lid & 7)) * 128 + (kp * 4 + (lid >> 3)) * 16));
                    mma_fp(acc4[f4], aQ[2 * kp], b);
                    mma_fp(acc4[f4], aQ[2 * kp + 1], b + 2);
                }
            }
            // --- epilogue: masked exp, normalize, stream-store, W frags ---
            unsigned w0 = m0a[c], w1 = m1a[c];
            uint32_t wv[4][2];
#pragma unroll
            for (int f4 = 0; f4 < 4; f4++) {
                int bit = 8 * f4 + 2 * t;
                float e0 = ((w0 >> bit) & 1)       ? __expf(acc4[f4][0]) * iv0 : 0.f;
                float e1 = ((w0 >> (bit + 1)) & 1) ? __expf(acc4[f4][1]) * iv0 : 0.f;
                float e2 = ((w1 >> bit) & 1)       ? __expf(acc4[f4][2]) * iv1 : 0.f;
                float e3 = ((w1 >> (bit + 1)) & 1) ? __expf(acc4[f4][3]) * iv1 : 0.f;
                int col = kt * 128 + 32 * c + 8 * f4 + 2 * t;
                stg_cs_f2(&attnb[(size_t)(q0 + r0l) * S + col], make_float2(e0, e1));
                stg_cs_f2(&attnb[(size_t)(q0 + r1l) * S + col], make_float2(e2, e3));
                __half2 h01 = __floats2half2_rn(e0, e1);
                __half2 h23 = __floats2half2_rn(e2, e3);
                wv[f4][0] = *(uint32_t*)&h01;
                wv[f4][1] = *(uint32_t*)&h23;
            }
            // --- GEMM2 partial: ctx += W[:,32c..32c+31] @ V[32c..32c+31,:] ---
            uint32_t aH0[4] = {wv[0][0], wv[0][1], wv[1][0], wv[1][1]};
            uint32_t aH1[4] = {wv[2][0], wv[2][1], wv[3][0], wv[3][1]};
#pragma unroll
            for (int n8 = 0; n8 < 8; n8++) {
                uint32_t bh[4];
                ldsm4t(bh, sb + vhb + SWZ((c * 32 + lid) * 128 + n8 * 16));
                mma_fp(ctxa[n8], aH0, bh);
                mma_fp(ctxa[n8], aH1, bh + 2);
            }
        }
    }

    // ---- ctx store ----
#pragma unroll
    for (int n8 = 0; n8 < 8; n8++) {
        int c = 8 * n8 + 2 * t;
        stg_cs_f2(&ctx[((size_t)nh * S + q0 + r0l) * D + c], make_float2(ctxa[n8][0], ctxa[n8][1]));
        stg_cs_f2(&ctx[((size_t)nh * S + q0 + r1l) * D + c], make_float2(ctxa[n8][2], ctxa[n8][3]));
    }
}

// ---------------------------------------------------------------------------
extern "C" void kernel_launch(void* const* d_in, const int* in_sizes, int n_in,
                              void* d_out, int out_size) {
    const float* q = (const float*)d_in[0];
    const float* k = (const float*)d_in[1];
    const float* v = (const float*)d_in[2];
    const int*   m = (const int*)d_in[3];

    float* ctx  = (float*)d_out;
    float* attn = (float*)d_out + CTX_ELEMS;

    cudaFuncSetAttribute(k_attn, cudaFuncAttributeMaxDynamicSharedMemorySize, SMEM_T);

    k_softmax_q<<<dim3(NH, 8), 256>>>(q);
    k_softmax_k<<<(NB * S * D + 255) / 256, 256>>>(k);
    k_pack_mask<<<(S * SW + 255) / 256, 256>>>(m);
    k_vhalf<<<(NB * HH * S * D / 4 + 255) / 256, 256>>>(v);
    k_attn<<<dim3(16, NH), 256, SMEM_T>>>(attn, ctx);
}

// round 14
// speedup vs baseline: 2.2711x; 1.1421x over previous
#include <cuda_runtime.h>
#include <cuda_fp16.h>
#include <cstdint>

#define S 2048
#define D 64
#define NB 2
#define HH 8
#define NH 16
#define SW 64                      /* S/32 mask words per row */
#define CTX_ELEMS (NB*HH*S*D)
#define LOG2E 1.4426950408889634f

// ---------------- scratch (__device__ globals; no allocations) --------------
__device__ __half    g_Qh[NB*HH*S*D];   // softmaxed Q, fp16
__device__ __half    g_Kh[NB*HH*S*D];   // softmaxed K, fp16
__device__ __half    g_Vf[NB*HH*S*D];   // V, fp16
__device__ unsigned  g_mb[S*SW];        // packed mask bits

#define SWZ(o) ((o) ^ (((o) >> 3) & 0x70))

__device__ __forceinline__ uint32_t smem_u32(const void* p) {
    uint32_t a;
    asm("{ .reg .u64 t; cvta.to.shared.u64 t, %1; cvt.u32.u64 %0, t; }" : "=r"(a) : "l"(p));
    return a;
}
__device__ __forceinline__ void cpa16(uint32_t dst, const void* src) {
    asm volatile("cp.async.cg.shared.global [%0], [%1], 16;"
                 :: "r"(dst), "l"(__cvta_generic_to_global(src)) : "memory");
}
#define CPA_COMMIT() asm volatile("cp.async.commit_group;" ::: "memory")
#define CPA_WAIT0()  asm volatile("cp.async.wait_group 0;" ::: "memory")

__device__ __forceinline__ void ldsm4(uint32_t* r, uint32_t a) {
    asm volatile("ldmatrix.sync.aligned.m8n8.x4.shared.b16 {%0,%1,%2,%3}, [%4];"
                 : "=r"(r[0]), "=r"(r[1]), "=r"(r[2]), "=r"(r[3]) : "r"(a));
}
__device__ __forceinline__ void ldsm4t(uint32_t* r, uint32_t a) {
    asm volatile("ldmatrix.sync.aligned.m8n8.x4.trans.shared.b16 {%0,%1,%2,%3}, [%4];"
                 : "=r"(r[0]), "=r"(r[1]), "=r"(r[2]), "=r"(r[3]) : "r"(a));
}
__device__ __forceinline__ void mma_fp(float* c, const uint32_t* a, const uint32_t* b) {
    asm volatile("mma.sync.aligned.m16n8k16.row.col.f32.f16.f16.f32 "
                 "{%0,%1,%2,%3}, {%4,%5,%6,%7}, {%8,%9}, {%0,%1,%2,%3};"
                 : "+f"(c[0]), "+f"(c[1]), "+f"(c[2]), "+f"(c[3])
                 : "r"(a[0]), "r"(a[1]), "r"(a[2]), "r"(a[3]), "r"(b[0]), "r"(b[1]));
}
__device__ __forceinline__ void stg_cs_f2(float* p, float2 v) {
    asm volatile("st.global.cs.v2.f32 [%0], {%1, %2};"
                 :: "l"(__cvta_generic_to_global(p)), "f"(v.x), "f"(v.y) : "memory");
}
__device__ __forceinline__ uint32_t h2exp2u(uint32_t x) {
    uint32_t r;
    asm("ex2.approx.f16x2 %0, %1;" : "=r"(r) : "r"(x));
    return r;
}

// ---------------------------------------------------------------------------
// softmax over axis=2 (sequence) for Q -> fp16
// ---------------------------------------------------------------------------
__global__ void k_softmax_q(const float* __restrict__ q) {
    int nh = blockIdx.x, dchunk = blockIdx.y;
    int dloc = threadIdx.x & 7, sy = threadIdx.x >> 3;
    int d = dchunk * 8 + dloc;
    const float* base = q + (size_t)nh * S * D + d;
    float sum = 0.f;
    for (int s = sy; s < S; s += 32) sum += __expf(base[(size_t)s * D]);
    __shared__ float red[32][8];
    red[sy][dloc] = sum;
    __syncthreads();
    for (int off = 16; off > 0; off >>= 1) {
        if (sy < off) red[sy][dloc] += red[sy + off][dloc];
        __syncthreads();
    }
    float iv = 1.f / red[0][dloc];
    __half* out = g_Qh + (size_t)nh * S * D + d;
    for (int s = sy; s < S; s += 32)
        out[(size_t)s * D] = __float2half_rn(__expf(base[(size_t)s * D]) * iv);
}

// ---------------------------------------------------------------------------
// softmax over axis=1 (heads) for K -> fp16
// ---------------------------------------------------------------------------
__global__ void k_softmax_k(const float* __restrict__ k) {
    int idx = blockIdx.x * blockDim.x + threadIdx.x;
    if (idx >= NB * S * D) return;
    int n = idx / (S * D);
    int sd = idx - n * (S * D);
    const float* p = k + (size_t)n * HH * S * D + sd;
    __half* o = g_Kh + (size_t)n * HH * S * D + sd;
    float e[HH]; float sum = 0.f;
#pragma unroll
    for (int h = 0; h < HH; h++) { e[h] = __expf(p[(size_t)h * S * D]); sum += e[h]; }
    float iv = 1.f / sum;
#pragma unroll
    for (int h = 0; h < HH; h++) o[(size_t)h * S * D] = __float2half_rn(e[h] * iv);
}

// ---------------------------------------------------------------------------
// pack mask bits
// ---------------------------------------------------------------------------
__global__ void k_pack_mask(const int* __restrict__ m) {
    int idx = blockIdx.x * blockDim.x + threadIdx.x;
    if (idx >= S * SW) return;
    int qq = idx >> 6, w = idx & 63;
    const int* p = m + (size_t)qq * S + w * 32;
    unsigned bits = 0;
#pragma unroll
    for (int b = 0; b < 32; b++) if (p[b] != 0) bits |= (1u << b);
    g_mb[idx] = bits;
}

// ---------------------------------------------------------------------------
// V convert: g_Vf = fp16(V)
// ---------------------------------------------------------------------------
__global__ void k_vhalf(const float* __restrict__ v) {
    int idx = blockIdx.x * blockDim.x + threadIdx.x;   // over quads
    if (idx >= NB * HH * S * D / 4) return;
    float4 f = *(const float4*)(v + (size_t)idx * 4);
    __half2 h01 = __floats2half2_rn(f.x, f.y);
    __half2 h23 = __floats2half2_rn(f.z, f.w);
    *(uint2*)(g_Vf + (size_t)idx * 4) = make_uint2(*(uint32_t*)&h01, *(uint32_t*)&h23);
}

// ---------------------------------------------------------------------------
// fused attention, cp.async double-buffered, fp16 MMA path
//   pass1: GEMM1 (pipelined B-LDSM) + masked f16x2-exp -> row sums
//   pass2: GEMM1 (pipelined), normalize, stream attn fp32, GEMM2 (pipelined V)
// ---------------------------------------------------------------------------
#define O_INVL 0
#define O_MB0  512
#define O_MB1  2560
#define O_KB0  4608
#define O_KB1  20992    /* also Q tile during prologue */
#define O_VH0  37376
#define O_VH1  53760
#define SMEM_T 70144

__global__ void __launch_bounds__(256, 2) k_attn(float* __restrict__ attn,
                                                 float* __restrict__ ctx) {
    extern __shared__ char smem[];
    const int tid = threadIdx.x, wid = tid >> 5, lid = tid & 31;
    const int g = lid >> 2, t = lid & 3;
    const int nh = blockIdx.y, q0 = blockIdx.x * 128;
    const uint32_t sb = smem_u32(smem);
    float* invl = (float*)(smem + O_INVL);

    const __half* Qg = g_Qh + ((size_t)nh * S + q0) * D;
    const __half* Kg = g_Kh + (size_t)nh * S * D;
    const __half* Vg = g_Vf + (size_t)nh * S * D;
    float* attnb = attn + (size_t)nh * S * S;

    // ---- prefetch K tile 0 + mask 0 into buf 0 (overlaps Q load/hoist) ----
    {
#pragma unroll
        for (int i = 0; i < 4; i++) {
            int idx = i * 256 + tid;
            int r = idx >> 3, s16 = idx & 7;
            cpa16(sb + O_KB0 + SWZ(r * 128 + s16 * 16), Kg + (size_t)r * 64 + s16 * 8);
        }
        if (tid < 128)
            cpa16(sb + O_MB0 + tid * 16, g_mb + (size_t)(q0 + tid) * SW);
        CPA_COMMIT();
    }

    // ---- load Q tile into KB1 region, hoist fragments, then recycle ----
#pragma unroll
    for (int i = 0; i < 4; i++) {
        int idx = i * 256 + tid;
        int r = idx >> 3, s16 = idx & 7;
        *(uint4*)(smem + O_KB1 + SWZ(r * 128 + s16 * 16)) =
            *(const uint4*)(Qg + (size_t)r * 64 + s16 * 8);
    }
    __syncthreads();
    uint32_t aQ[4][4];
#pragma unroll
    for (int kk = 0; kk < 4; kk++) {
        int rl = 16 * wid + (lid & 7) + (lid & 8);
        int c16 = kk * 2 + (lid >> 4);
        ldsm4(aQ[kk], sb + O_KB1 + SWZ(rl * 128 + c16 * 16));
    }
    __syncthreads();   // Q region now reusable as K buffer 1

    const int r0l = 16 * wid + g, r1l = r0l + 8;

    // ================= pass 1: row sums (pipelined B-LDSM, f16x2 exp) ======
    float rs0 = 0.f, rs1 = 0.f;
    for (int kt = 0; kt < 16; kt++) {
        CPA_WAIT0();
        __syncthreads();
        if (kt < 15) {   // prefetch kt+1
            int b = (kt + 1) & 1;
            uint32_t kb = b ? O_KB1 : O_KB0, mb = b ? O_MB1 : O_MB0;
#pragma unroll
            for (int i = 0; i < 4; i++) {
                int idx = i * 256 + tid;
                int r = idx >> 3, s16 = idx & 7;
                cpa16(sb + kb + SWZ(r * 128 + s16 * 16),
                      Kg + (size_t)((kt + 1) * 128 + r) * 64 + s16 * 8);
            }
            if (tid < 128)
                cpa16(sb + mb + tid * 16, g_mb + (size_t)(q0 + tid) * SW + (kt + 1) * 4);
            CPA_COMMIT();
        }
        const uint32_t kb = (kt & 1) ? O_KB1 : O_KB0;
        const uint32_t mb = (kt & 1) ? O_MB1 : O_MB0;

        uint4 mw0 = *(uint4*)(smem + mb + r0l * 16);
        uint4 mw1 = *(uint4*)(smem + mb + r1l * 16);
        unsigned m0a[4] = {mw0.x, mw0.y, mw0.z, mw0.w};
        unsigned m1a[4] = {mw1.x, mw1.y, mw1.z, mw1.w};

        // flat fragment loop with one-step B lookahead
        float acc4[4][4];
        uint32_t bn[8], bc[8];
        ldsm4(bn,     sb + kb + SWZ((0 * 8 + (lid & 7)) * 128 + (0 * 4 + (lid >> 3)) * 16));
        ldsm4(bn + 4, sb + kb + SWZ((0 * 8 + (lid & 7)) * 128 + (1 * 4 + (lid >> 3)) * 16));
#pragma unroll
        for (int f = 0; f < 16; f++) {
            const int f4 = f & 3;
#pragma unroll
            for (int j = 0; j < 8; j++) bc[j] = bn[j];
            if (f < 15) {
                ldsm4(bn,     sb + kb + SWZ(((f + 1) * 8 + (lid & 7)) * 128 + (0 * 4 + (lid >> 3)) * 16));
                ldsm4(bn + 4, sb + kb + SWZ(((f + 1) * 8 + (lid & 7)) * 128 + (1 * 4 + (lid >> 3)) * 16));
            }
            acc4[f4][0] = acc4[f4][1] = acc4[f4][2] = acc4[f4][3] = 0.f;
            mma_fp(acc4[f4], aQ[0], bc);
            mma_fp(acc4[f4], aQ[1], bc + 2);
            mma_fp(acc4[f4], aQ[2], bc + 4);
            mma_fp(acc4[f4], aQ[3], bc + 6);
            if (f4 == 3) {
                const int c = f >> 2;
                unsigned w0 = m0a[c], w1 = m1a[c];
#pragma unroll
                for (int u = 0; u < 4; u++) {
                    int bit = 8 * u + 2 * t;
                    __half2 x01 = __floats2half2_rn(acc4[u][0] * LOG2E, acc4[u][1] * LOG2E);
                    __half2 x23 = __floats2half2_rn(acc4[u][2] * LOG2E, acc4[u][3] * LOG2E);
                    uint32_t e01 = h2exp2u(*(uint32_t*)&x01);
                    uint32_t e23 = h2exp2u(*(uint32_t*)&x23);
                    float2 f01 = __half22float2(*(__half2*)&e01);
                    float2 f23 = __half22float2(*(__half2*)&e23);
                    if ((w0 >> bit) & 1)       rs0 += f01.x;
                    if ((w0 >> (bit + 1)) & 1) rs0 += f01.y;
                    if ((w1 >> bit) & 1)       rs1 += f23.x;
                    if ((w1 >> (bit + 1)) & 1) rs1 += f23.y;
                }
            }
        }
    }

    // ---- prefetch pass-2 tile 0 early (overlaps reduction) ----
    {
#pragma unroll
        for (int i = 0; i < 4; i++) {
            int idx = i * 256 + tid;
            int r = idx >> 3, s16 = idx & 7;
            uint32_t swo = SWZ(r * 128 + s16 * 16);
            size_t gofs = (size_t)r * 64 + s16 * 8;
            cpa16(sb + O_KB0 + swo, Kg + gofs);
            cpa16(sb + O_VH0 + swo, Vg + gofs);
        }
        if (tid < 128)
            cpa16(sb + O_MB0 + tid * 16, g_mb + (size_t)(q0 + tid) * SW);
        CPA_COMMIT();
    }

    rs0 += __shfl_xor_sync(0xffffffffu, rs0, 1);
    rs0 += __shfl_xor_sync(0xffffffffu, rs0, 2);
    rs1 += __shfl_xor_sync(0xffffffffu, rs1, 1);
    rs1 += __shfl_xor_sync(0xffffffffu, rs1, 2);
    if (t == 0) {
        invl[r0l] = rs0 > 0.f ? 1.f / rs0 : 0.f;
        invl[r1l] = rs1 > 0.f ? 1.f / rs1 : 0.f;
    }
    __syncthreads();
    const float iv0 = invl[r0l], iv1 = invl[r1l];

    // ================= pass 2: recompute + normalize + chunked GEMM2 ========
    float ctxa[8][4];
#pragma unroll
    for (int n = 0; n < 8; n++) { ctxa[n][0] = ctxa[n][1] = ctxa[n][2] = ctxa[n][3] = 0.f; }

    for (int kt = 0; kt < 16; kt++) {
        CPA_WAIT0();
        __syncthreads();
        if (kt < 15) {   // prefetch kt+1
            int b = (kt + 1) & 1;
            uint32_t kb = b ? O_KB1 : O_KB0, vh = b ? O_VH1 : O_VH0;
            uint32_t mb = b ? O_MB1 : O_MB0;
#pragma unroll
            for (int i = 0; i < 4; i++) {
                int idx = i * 256 + tid;
                int r = idx >> 3, s16 = idx & 7;
                uint32_t swo = SWZ(r * 128 + s16 * 16);
                size_t gofs = (size_t)((kt + 1) * 128 + r) * 64 + s16 * 8;
                cpa16(sb + kb + swo, Kg + gofs);
                cpa16(sb + vh + swo, Vg + gofs);
            }
            if (tid < 128)
                cpa16(sb + mb + tid * 16, g_mb + (size_t)(q0 + tid) * SW + (kt + 1) * 4);
            CPA_COMMIT();
        }
        const int bsel = kt & 1;
        const uint32_t kb  = bsel ? O_KB1 : O_KB0;
        const uint32_t vhb = bsel ? O_VH1 : O_VH0;
        const uint32_t mb  = bsel ? O_MB1 : O_MB0;

        uint4 mw0 = *(uint4*)(smem + mb + r0l * 16);
        uint4 mw1 = *(uint4*)(smem + mb + r1l * 16);
        unsigned m0a[4] = {mw0.x, mw0.y, mw0.z, mw0.w};
        unsigned m1a[4] = {mw1.x, mw1.y, mw1.z, mw1.w};

#pragma unroll
        for (int c = 0; c < 4; c++) {
            // --- GEMM1 for 4 fragments (32 attn cols), pipelined B loads ---
            float acc4[4][4];
            uint32_t bn[8], bc[8];
            {
                int f = 4 * c;
                ldsm4(bn,     sb + kb + SWZ((f * 8 + (lid & 7)) * 128 + (0 * 4 + (lid >> 3)) * 16));
                ldsm4(bn + 4, sb + kb + SWZ((f * 8 + (lid & 7)) * 128 + (1 * 4 + (lid >> 3)) * 16));
            }
#pragma unroll
            for (int f4 = 0; f4 < 4; f4++) {
#pragma unroll
                for (int j = 0; j < 8; j++) bc[j] = bn[j];
                if (f4 < 3) {
                    int f = 4 * c + f4 + 1;
                    ldsm4(bn,     sb + kb + SWZ((f * 8 + (lid & 7)) * 128 + (0 * 4 + (lid >> 3)) * 16));
                    ldsm4(bn + 4, sb + kb + SWZ((f * 8 + (lid & 7)) * 128 + (1 * 4 + (lid >> 3)) * 16));
                }
                acc4[f4][0] = acc4[f4][1] = acc4[f4][2] = acc4[f4][3] = 0.f;
                mma_fp(acc4[f4], aQ[0], bc);
                mma_fp(acc4[f4], aQ[1], bc + 2);
                mma_fp(acc4[f4], aQ[2], bc + 4);
                mma_fp(acc4[f4], aQ[3], bc + 6);
            }
            // --- epilogue: masked exp, normalize, stream-store, W frags ---
            unsigned w0 = m0a[c], w1 = m1a[c];
            uint32_t wv[4][2];
#pragma unroll
            for (int f4 = 0; f4 < 4; f4++) {
                int bit = 8 * f4 + 2 * t;
                float e0 = ((w0 >> bit) & 1)       ? __expf(acc4[f4][0]) * iv0 : 0.f;
                float e1 = ((w0 >> (bit + 1)) & 1) ? __expf(acc4[f4][1]) * iv0 : 0.f;
                float e2 = ((w1 >> bit) & 1)       ? __expf(acc4[f4][2]) * iv1 : 0.f;
                float e3 = ((w1 >> (bit + 1)) & 1) ? __expf(acc4[f4][3]) * iv1 : 0.f;
                int col = kt * 128 + 32 * c + 8 * f4 + 2 * t;
                stg_cs_f2(&attnb[(size_t)(q0 + r0l) * S + col], make_float2(e0, e1));
                stg_cs_f2(&attnb[(size_t)(q0 + r1l) * S + col], make_float2(e2, e3));
                __half2 h01 = __floats2half2_rn(e0, e1);
                __half2 h23 = __floats2half2_rn(e2, e3);
                wv[f4][0] = *(uint32_t*)&h01;
                wv[f4][1] = *(uint32_t*)&h23;
            }
            // --- GEMM2 partial, pipelined V loads ---
            uint32_t aH0[4] = {wv[0][0], wv[0][1], wv[1][0], wv[1][1]};
            uint32_t aH1[4] = {wv[2][0], wv[2][1], wv[3][0], wv[3][1]};
            uint32_t bhn[4], bhc[4];
            ldsm4t(bhn, sb + vhb + SWZ((c * 32 + lid) * 128 + 0 * 16));
#pragma unroll
            for (int n8 = 0; n8 < 8; n8++) {
#pragma unroll
                for (int j = 0; j < 4; j++) bhc[j] = bhn[j];
                if (n8 < 7)
                    ldsm4t(bhn, sb + vhb + SWZ((c * 32 + lid) * 128 + (n8 + 1) * 16));
                mma_fp(ctxa[n8], aH0, bhc);
                mma_fp(ctxa[n8], aH1, bhc + 2);
            }
        }
    }

    // ---- ctx store ----
#pragma unroll
    for (int n8 = 0; n8 < 8; n8++) {
        int c = 8 * n8 + 2 * t;
        stg_cs_f2(&ctx[((size_t)nh * S + q0 + r0l) * D + c], make_float2(ctxa[n8][0], ctxa[n8][1]));
        stg_cs_f2(&ctx[((size_t)nh * S + q0 + r1l) * D + c], make_float2(ctxa[n8][2], ctxa[n8][3]));
    }
}

// ---------------------------------------------------------------------------
extern "C" void kernel_launch(void* const* d_in, const int* in_sizes, int n_in,
                              void* d_out, int out_size) {
    const float* q = (const float*)d_in[0];
    const float* k = (const float*)d_in[1];
    const float* v = (const float*)d_in[2];
    const int*   m = (const int*)d_in[3];

    float* ctx  = (float*)d_out;
    float* attn = (float*)d_out + CTX_ELEMS;

    cudaFuncSetAttribute(k_attn, cudaFuncAttributeMaxDynamicSharedMemorySize, SMEM_T);

    k_softmax_q<<<dim3(NH, 8), 256>>>(q);
    k_softmax_k<<<(NB * S * D + 255) / 256, 256>>>(k);
    k_pack_mask<<<(S * SW + 255) / 256, 256>>>(m);
    k_vhalf<<<(NB * HH * S * D / 4 + 255) / 256, 256>>>(v);
    k_attn<<<dim3(16, NH), 256, SMEM_T>>>(attn, ctx);
}

// round 15
// speedup vs baseline: 2.3284x; 1.0252x over previous
#include <cuda_runtime.h>
#include <cuda_fp16.h>
#include <cstdint>

#define S 2048
#define D 64
#define NB 2
#define HH 8
#define NH 16
#define SW 64                      /* S/32 mask words per row */
#define CTX_ELEMS (NB*HH*S*D)
#define LOG2E 1.4426950408889634f

// ---------------- scratch (__device__ globals; no allocations) --------------
__device__ __half    g_Qh[NB*HH*S*D];   // softmaxed Q, fp16
__device__ __half    g_Kh[NB*HH*S*D];   // softmaxed K, fp16
__device__ __half    g_Vf[NB*HH*S*D];   // V, fp16
__device__ unsigned  g_mb[S*SW];        // packed mask bits

#define SWZ(o) ((o) ^ (((o) >> 3) & 0x70))

__device__ __forceinline__ uint32_t smem_u32(const void* p) {
    uint32_t a;
    asm("{ .reg .u64 t; cvta.to.shared.u64 t, %1; cvt.u32.u64 %0, t; }" : "=r"(a) : "l"(p));
    return a;
}
__device__ __forceinline__ void cpa16(uint32_t dst, const void* src) {
    asm volatile("cp.async.cg.shared.global [%0], [%1], 16;"
                 :: "r"(dst), "l"(__cvta_generic_to_global(src)) : "memory");
}
#define CPA_COMMIT() asm volatile("cp.async.commit_group;" ::: "memory")
#define CPA_WAIT0()  asm volatile("cp.async.wait_group 0;" ::: "memory")

__device__ __forceinline__ void ldsm4(uint32_t* r, uint32_t a) {
    asm volatile("ldmatrix.sync.aligned.m8n8.x4.shared.b16 {%0,%1,%2,%3}, [%4];"
                 : "=r"(r[0]), "=r"(r[1]), "=r"(r[2]), "=r"(r[3]) : "r"(a));
}
__device__ __forceinline__ void ldsm4t(uint32_t* r, uint32_t a) {
    asm volatile("ldmatrix.sync.aligned.m8n8.x4.trans.shared.b16 {%0,%1,%2,%3}, [%4];"
                 : "=r"(r[0]), "=r"(r[1]), "=r"(r[2]), "=r"(r[3]) : "r"(a));
}
__device__ __forceinline__ void mma_fp(float* c, const uint32_t* a, const uint32_t* b) {
    asm volatile("mma.sync.aligned.m16n8k16.row.col.f32.f16.f16.f32 "
                 "{%0,%1,%2,%3}, {%4,%5,%6,%7}, {%8,%9}, {%0,%1,%2,%3};"
                 : "+f"(c[0]), "+f"(c[1]), "+f"(c[2]), "+f"(c[3])
                 : "r"(a[0]), "r"(a[1]), "r"(a[2]), "r"(a[3]), "r"(b[0]), "r"(b[1]));
}
__device__ __forceinline__ void stg_cs_f2(float* p, float2 v) {
    asm volatile("st.global.cs.v2.f32 [%0], {%1, %2};"
                 :: "l"(__cvta_generic_to_global(p)), "f"(v.x), "f"(v.y) : "memory");
}
__device__ __forceinline__ uint32_t h2exp2u(uint32_t x) {
    uint32_t r;
    asm("ex2.approx.f16x2 %0, %1;" : "=r"(r) : "r"(x));
    return r;
}

// ---------------------------------------------------------------------------
// softmax over axis=2 (sequence) for Q -> fp16
// ---------------------------------------------------------------------------
__global__ void k_softmax_q(const float* __restrict__ q) {
    int nh = blockIdx.x, dchunk = blockIdx.y;
    int dloc = threadIdx.x & 7, sy = threadIdx.x >> 3;
    int d = dchunk * 8 + dloc;
    const float* base = q + (size_t)nh * S * D + d;
    float sum = 0.f;
    for (int s = sy; s < S; s += 32) sum += __expf(base[(size_t)s * D]);
    __shared__ float red[32][8];
    red[sy][dloc] = sum;
    __syncthreads();
    for (int off = 16; off > 0; off >>= 1) {
        if (sy < off) red[sy][dloc] += red[sy + off][dloc];
        __syncthreads();
    }
    float iv = 1.f / red[0][dloc];
    __half* out = g_Qh + (size_t)nh * S * D + d;
    for (int s = sy; s < S; s += 32)
        out[(size_t)s * D] = __float2half_rn(__expf(base[(size_t)s * D]) * iv);
}

// ---------------------------------------------------------------------------
// softmax over axis=1 (heads) for K -> fp16
// ---------------------------------------------------------------------------
__global__ void k_softmax_k(const float* __restrict__ k) {
    int idx = blockIdx.x * blockDim.x + threadIdx.x;
    if (idx >= NB * S * D) return;
    int n = idx / (S * D);
    int sd = idx - n * (S * D);
    const float* p = k + (size_t)n * HH * S * D + sd;
    __half* o = g_Kh + (size_t)n * HH * S * D + sd;
    float e[HH]; float sum = 0.f;
#pragma unroll
    for (int h = 0; h < HH; h++) { e[h] = __expf(p[(size_t)h * S * D]); sum += e[h]; }
    float iv = 1.f / sum;
#pragma unroll
    for (int h = 0; h < HH; h++) o[(size_t)h * S * D] = __float2half_rn(e[h] * iv);
}

// ---------------------------------------------------------------------------
// pack mask bits
// ---------------------------------------------------------------------------
__global__ void k_pack_mask(const int* __restrict__ m) {
    int idx = blockIdx.x * blockDim.x + threadIdx.x;
    if (idx >= S * SW) return;
    int qq = idx >> 6, w = idx & 63;
    const int* p = m + (size_t)qq * S + w * 32;
    unsigned bits = 0;
#pragma unroll
    for (int b = 0; b < 32; b++) if (p[b] != 0) bits |= (1u << b);
    g_mb[idx] = bits;
}

// ---------------------------------------------------------------------------
// V convert: g_Vf = fp16(V)
// ---------------------------------------------------------------------------
__global__ void k_vhalf(const float* __restrict__ v) {
    int idx = blockIdx.x * blockDim.x + threadIdx.x;   // over quads
    if (idx >= NB * HH * S * D / 4) return;
    float4 f = *(const float4*)(v + (size_t)idx * 4);
    __half2 h01 = __floats2half2_rn(f.x, f.y);
    __half2 h23 = __floats2half2_rn(f.z, f.w);
    *(uint2*)(g_Vf + (size_t)idx * 4) = make_uint2(*(uint32_t*)&h01, *(uint32_t*)&h23);
}

// ---------------------------------------------------------------------------
// fused attention, cp.async double-buffered, fp16 MMA path
//   pass1: GEMM1 (pipelined B-LDSM) + masked f16x2-exp -> row sums
//   pass2: GEMM1 (pipelined), f16x2-exp (same bias as pass1 -> cancels in e/l),
//          normalize, stream attn fp32, GEMM2 (pipelined V)
// ---------------------------------------------------------------------------
#define O_INVL 0
#define O_MB0  512
#define O_MB1  2560
#define O_KB0  4608
#define O_KB1  20992    /* also Q tile during prologue */
#define O_VH0  37376
#define O_VH1  53760
#define SMEM_T 70144

__global__ void __launch_bounds__(256, 2) k_attn(float* __restrict__ attn,
                                                 float* __restrict__ ctx) {
    extern __shared__ char smem[];
    const int tid = threadIdx.x, wid = tid >> 5, lid = tid & 31;
    const int g = lid >> 2, t = lid & 3;
    const int nh = blockIdx.y, q0 = blockIdx.x * 128;
    const uint32_t sb = smem_u32(smem);
    float* invl = (float*)(smem + O_INVL);

    const __half* Qg = g_Qh + ((size_t)nh * S + q0) * D;
    const __half* Kg = g_Kh + (size_t)nh * S * D;
    const __half* Vg = g_Vf + (size_t)nh * S * D;
    float* attnb = attn + (size_t)nh * S * S;

    // ---- prefetch K tile 0 + mask 0 into buf 0 (overlaps Q load/hoist) ----
    {
#pragma unroll
        for (int i = 0; i < 4; i++) {
            int idx = i * 256 + tid;
            int r = idx >> 3, s16 = idx & 7;
            cpa16(sb + O_KB0 + SWZ(r * 128 + s16 * 16), Kg + (size_t)r * 64 + s16 * 8);
        }
        if (tid < 128)
            cpa16(sb + O_MB0 + tid * 16, g_mb + (size_t)(q0 + tid) * SW);
        CPA_COMMIT();
    }

    // ---- load Q tile into KB1 region, hoist fragments, then recycle ----
#pragma unroll
    for (int i = 0; i < 4; i++) {
        int idx = i * 256 + tid;
        int r = idx >> 3, s16 = idx & 7;
        *(uint4*)(smem + O_KB1 + SWZ(r * 128 + s16 * 16)) =
            *(const uint4*)(Qg + (size_t)r * 64 + s16 * 8);
    }
    __syncthreads();
    uint32_t aQ[4][4];
#pragma unroll
    for (int kk = 0; kk < 4; kk++) {
        int rl = 16 * wid + (lid & 7) + (lid & 8);
        int c16 = kk * 2 + (lid >> 4);
        ldsm4(aQ[kk], sb + O_KB1 + SWZ(rl * 128 + c16 * 16));
    }
    __syncthreads();   // Q region now reusable as K buffer 1

    const int r0l = 16 * wid + g, r1l = r0l + 8;

    // ================= pass 1: row sums (pipelined B-LDSM, f16x2 exp) ======
    float rs0 = 0.f, rs1 = 0.f;
    for (int kt = 0; kt < 16; kt++) {
        CPA_WAIT0();
        __syncthreads();
        if (kt < 15) {   // prefetch kt+1
            int b = (kt + 1) & 1;
            uint32_t kb = b ? O_KB1 : O_KB0, mb = b ? O_MB1 : O_MB0;
#pragma unroll
            for (int i = 0; i < 4; i++) {
                int idx = i * 256 + tid;
                int r = idx >> 3, s16 = idx & 7;
                cpa16(sb + kb + SWZ(r * 128 + s16 * 16),
                      Kg + (size_t)((kt + 1) * 128 + r) * 64 + s16 * 8);
            }
            if (tid < 128)
                cpa16(sb + mb + tid * 16, g_mb + (size_t)(q0 + tid) * SW + (kt + 1) * 4);
            CPA_COMMIT();
        }
        const uint32_t kb = (kt & 1) ? O_KB1 : O_KB0;
        const uint32_t mb = (kt & 1) ? O_MB1 : O_MB0;

        uint4 mw0 = *(uint4*)(smem + mb + r0l * 16);
        uint4 mw1 = *(uint4*)(smem + mb + r1l * 16);
        unsigned m0a[4] = {mw0.x, mw0.y, mw0.z, mw0.w};
        unsigned m1a[4] = {mw1.x, mw1.y, mw1.z, mw1.w};

        // flat fragment loop with one-step B lookahead
        float acc4[4][4];
        uint32_t bn[8], bc[8];
        ldsm4(bn,     sb + kb + SWZ((0 * 8 + (lid & 7)) * 128 + (0 * 4 + (lid >> 3)) * 16));
        ldsm4(bn + 4, sb + kb + SWZ((0 * 8 + (lid & 7)) * 128 + (1 * 4 + (lid >> 3)) * 16));
#pragma unroll
        for (int f = 0; f < 16; f++) {
            const int f4 = f & 3;
#pragma unroll
            for (int j = 0; j < 8; j++) bc[j] = bn[j];
            if (f < 15) {
                ldsm4(bn,     sb + kb + SWZ(((f + 1) * 8 + (lid & 7)) * 128 + (0 * 4 + (lid >> 3)) * 16));
                ldsm4(bn + 4, sb + kb + SWZ(((f + 1) * 8 + (lid & 7)) * 128 + (1 * 4 + (lid >> 3)) * 16));
            }
            acc4[f4][0] = acc4[f4][1] = acc4[f4][2] = acc4[f4][3] = 0.f;
            mma_fp(acc4[f4], aQ[0], bc);
            mma_fp(acc4[f4], aQ[1], bc + 2);
            mma_fp(acc4[f4], aQ[2], bc + 4);
            mma_fp(acc4[f4], aQ[3], bc + 6);
            if (f4 == 3) {
                const int c = f >> 2;
                unsigned w0 = m0a[c], w1 = m1a[c];
#pragma unroll
                for (int u = 0; u < 4; u++) {
                    int bit = 8 * u + 2 * t;
                    __half2 x01 = __floats2half2_rn(acc4[u][0] * LOG2E, acc4[u][1] * LOG2E);
                    __half2 x23 = __floats2half2_rn(acc4[u][2] * LOG2E, acc4[u][3] * LOG2E);
                    uint32_t e01 = h2exp2u(*(uint32_t*)&x01);
                    uint32_t e23 = h2exp2u(*(uint32_t*)&x23);
                    float2 f01 = __half22float2(*(__half2*)&e01);
                    float2 f23 = __half22float2(*(__half2*)&e23);
                    if ((w0 >> bit) & 1)       rs0 += f01.x;
                    if ((w0 >> (bit + 1)) & 1) rs0 += f01.y;
                    if ((w1 >> bit) & 1)       rs1 += f23.x;
                    if ((w1 >> (bit + 1)) & 1) rs1 += f23.y;
                }
            }
        }
    }

    // ---- prefetch pass-2 tile 0 early (overlaps reduction) ----
    {
#pragma unroll
        for (int i = 0; i < 4; i++) {
            int idx = i * 256 + tid;
            int r = idx >> 3, s16 = idx & 7;
            uint32_t swo = SWZ(r * 128 + s16 * 16);
            size_t gofs = (size_t)r * 64 + s16 * 8;
            cpa16(sb + O_KB0 + swo, Kg + gofs);
            cpa16(sb + O_VH0 + swo, Vg + gofs);
        }
        if (tid < 128)
            cpa16(sb + O_MB0 + tid * 16, g_mb + (size_t)(q0 + tid) * SW);
        CPA_COMMIT();
    }

    rs0 += __shfl_xor_sync(0xffffffffu, rs0, 1);
    rs0 += __shfl_xor_sync(0xffffffffu, rs0, 2);
    rs1 += __shfl_xor_sync(0xffffffffu, rs1, 1);
    rs1 += __shfl_xor_sync(0xffffffffu, rs1, 2);
    if (t == 0) {
        invl[r0l] = rs0 > 0.f ? 1.f / rs0 : 0.f;
        invl[r1l] = rs1 > 0.f ? 1.f / rs1 : 0.f;
    }
    __syncthreads();
    const float iv0 = invl[r0l], iv1 = invl[r1l];

    // ================= pass 2: recompute + normalize + chunked GEMM2 ========
    float ctxa[8][4];
#pragma unroll
    for (int n = 0; n < 8; n++) { ctxa[n][0] = ctxa[n][1] = ctxa[n][2] = ctxa[n][3] = 0.f; }

    for (int kt = 0; kt < 16; kt++) {
        CPA_WAIT0();
        __syncthreads();
        if (kt < 15) {   // prefetch kt+1
            int b = (kt + 1) & 1;
            uint32_t kb = b ? O_KB1 : O_KB0, vh = b ? O_VH1 : O_VH0;
            uint32_t mb = b ? O_MB1 : O_MB0;
#pragma unroll
            for (int i = 0; i < 4; i++) {
                int idx = i * 256 + tid;
                int r = idx >> 3, s16 = idx & 7;
                uint32_t swo = SWZ(r * 128 + s16 * 16);
                size_t gofs = (size_t)((kt + 1) * 128 + r) * 64 + s16 * 8;
                cpa16(sb + kb + swo, Kg + gofs);
                cpa16(sb + vh + swo, Vg + gofs);
            }
            if (tid < 128)
                cpa16(sb + mb + tid * 16, g_mb + (size_t)(q0 + tid) * SW + (kt + 1) * 4);
            CPA_COMMIT();
        }
        const int bsel = kt & 1;
        const uint32_t kb  = bsel ? O_KB1 : O_KB0;
        const uint32_t vhb = bsel ? O_VH1 : O_VH0;
        const uint32_t mb  = bsel ? O_MB1 : O_MB0;

        uint4 mw0 = *(uint4*)(smem + mb + r0l * 16);
        uint4 mw1 = *(uint4*)(smem + mb + r1l * 16);
        unsigned m0a[4] = {mw0.x, mw0.y, mw0.z, mw0.w};
        unsigned m1a[4] = {mw1.x, mw1.y, mw1.z, mw1.w};

#pragma unroll
        for (int c = 0; c < 4; c++) {
            // --- GEMM1 for 4 fragments (32 attn cols), pipelined B loads ---
            float acc4[4][4];
            uint32_t bn[8], bc[8];
            {
                int f = 4 * c;
                ldsm4(bn,     sb + kb + SWZ((f * 8 + (lid & 7)) * 128 + (0 * 4 + (lid >> 3)) * 16));
                ldsm4(bn + 4, sb + kb + SWZ((f * 8 + (lid & 7)) * 128 + (1 * 4 + (lid >> 3)) * 16));
            }
#pragma unroll
            for (int f4 = 0; f4 < 4; f4++) {
#pragma unroll
                for (int j = 0; j < 8; j++) bc[j] = bn[j];
                if (f4 < 3) {
                    int f = 4 * c + f4 + 1;
                    ldsm4(bn,     sb + kb + SWZ((f * 8 + (lid & 7)) * 128 + (0 * 4 + (lid >> 3)) * 16));
                    ldsm4(bn + 4, sb + kb + SWZ((f * 8 + (lid & 7)) * 128 + (1 * 4 + (lid >> 3)) * 16));
                }
                acc4[f4][0] = acc4[f4][1] = acc4[f4][2] = acc4[f4][3] = 0.f;
                mma_fp(acc4[f4], aQ[0], bc);
                mma_fp(acc4[f4], aQ[1], bc + 2);
                mma_fp(acc4[f4], aQ[2], bc + 4);
                mma_fp(acc4[f4], aQ[3], bc + 6);
            }
            // --- epilogue: f16x2 exp (bias-matched to pass 1), mask,
            //     normalize fp32, stream-store, pack W frags ---
            unsigned w0 = m0a[c], w1 = m1a[c];
            uint32_t wv[4][2];
#pragma unroll
            for (int f4 = 0; f4 < 4; f4++) {
                int bit = 8 * f4 + 2 * t;
                __half2 x01 = __floats2half2_rn(acc4[f4][0] * LOG2E, acc4[f4][1] * LOG2E);
                __half2 x23 = __floats2half2_rn(acc4[f4][2] * LOG2E, acc4[f4][3] * LOG2E);
                uint32_t eu01 = h2exp2u(*(uint32_t*)&x01);
                uint32_t eu23 = h2exp2u(*(uint32_t*)&x23);
                float2 f01 = __half22float2(*(__half2*)&eu01);
                float2 f23 = __half22float2(*(__half2*)&eu23);
                float e0 = ((w0 >> bit) & 1)       ? f01.x * iv0 : 0.f;
                float e1 = ((w0 >> (bit + 1)) & 1) ? f01.y * iv0 : 0.f;
                float e2 = ((w1 >> bit) & 1)       ? f23.x * iv1 : 0.f;
                float e3 = ((w1 >> (bit + 1)) & 1) ? f23.y * iv1 : 0.f;
                int col = kt * 128 + 32 * c + 8 * f4 + 2 * t;
                stg_cs_f2(&attnb[(size_t)(q0 + r0l) * S + col], make_float2(e0, e1));
                stg_cs_f2(&attnb[(size_t)(q0 + r1l) * S + col], make_float2(e2, e3));
                __half2 h01 = __floats2half2_rn(e0, e1);
                __half2 h23 = __floats2half2_rn(e2, e3);
                wv[f4][0] = *(uint32_t*)&h01;
                wv[f4][1] = *(uint32_t*)&h23;
            }
            // --- GEMM2 partial, pipelined V loads ---
            uint32_t aH0[4] = {wv[0][0], wv[0][1], wv[1][0], wv[1][1]};
            uint32_t aH1[4] = {wv[2][0], wv[2][1], wv[3][0], wv[3][1]};
            uint32_t bhn[4], bhc[4];
            ldsm4t(bhn, sb + vhb + SWZ((c * 32 + lid) * 128 + 0 * 16));
#pragma unroll
            for (int n8 = 0; n8 < 8; n8++) {
#pragma unroll
                for (int j = 0; j < 4; j++) bhc[j] = bhn[j];
                if (n8 < 7)
                    ldsm4t(bhn, sb + vhb + SWZ((c * 32 + lid) * 128 + (n8 + 1) * 16));
                mma_fp(ctxa[n8], aH0, bhc);
                mma_fp(ctxa[n8], aH1, bhc + 2);
            }
        }
    }

    // ---- ctx store ----
#pragma unroll
    for (int n8 = 0; n8 < 8; n8++) {
        int c = 8 * n8 + 2 * t;
        stg_cs_f2(&ctx[((size_t)nh * S + q0 + r0l) * D + c], make_float2(ctxa[n8][0], ctxa[n8][1]));
        stg_cs_f2(&ctx[((size_t)nh * S + q0 + r1l) * D + c], make_float2(ctxa[n8][2], ctxa[n8][3]));
    }
}

// ---------------------------------------------------------------------------
extern "C" void kernel_launch(void* const* d_in, const int* in_sizes, int n_in,
                              void* d_out, int out_size) {
    const float* q = (const float*)d_in[0];
    const float* k = (const float*)d_in[1];
    const float* v = (const float*)d_in[2];
    const int*   m = (const int*)d_in[3];

    float* ctx  = (float*)d_out;
    float* attn = (float*)d_out + CTX_ELEMS;

    cudaFuncSetAttribute(k_attn, cudaFuncAttributeMaxDynamicSharedMemorySize, SMEM_T);

    k_softmax_q<<<dim3(NH, 8), 256>>>(q);
    k_softmax_k<<<(NB * S * D + 255) / 256, 256>>>(k);
    k_pack_mask<<<(S * SW + 255) / 256, 256>>>(m);
    k_vhalf<<<(NB * HH * S * D / 4 + 255) / 256, 256>>>(v);
    k_attn<<<dim3(16, NH), 256, SMEM_T>>>(attn, ctx);
}

// round 17
// speedup vs baseline: 2.3597x; 1.0134x over previous
#include <cuda_runtime.h>
#include <cuda_fp16.h>
#include <cstdint>

#define S 2048
#define D 64
#define NB 2
#define HH 8
#define NH 16
#define SW 64                      /* S/32 mask words per row */
#define CTX_ELEMS (NB*HH*S*D)
#define LOG2E 1.4426950408889634f

// ---------------- scratch (__device__ globals; no allocations) --------------
__device__ __half    g_Qh[NB*HH*S*D];   // softmaxed Q, fp16
__device__ __half    g_Kh[NB*HH*S*D];   // softmaxed K, fp16
__device__ __half    g_Vf[NB*HH*S*D];   // V, fp16
__device__ unsigned  g_mb[S*SW];        // packed mask bits
__device__ float     g_l [NB*HH*S];     // row sums of masked exp

#define SWZ(o) ((o) ^ (((o) >> 3) & 0x70))

__device__ __forceinline__ uint32_t smem_u32(const void* p) {
    uint32_t a;
    asm("{ .reg .u64 t; cvta.to.shared.u64 t, %1; cvt.u32.u64 %0, t; }" : "=r"(a) : "l"(p));
    return a;
}
__device__ __forceinline__ void cpa16(uint32_t dst, const void* src) {
    asm volatile("cp.async.cg.shared.global [%0], [%1], 16;"
                 :: "r"(dst), "l"(__cvta_generic_to_global(src)) : "memory");
}
#define CPA_COMMIT() asm volatile("cp.async.commit_group;" ::: "memory")
#define CPA_WAIT0()  asm volatile("cp.async.wait_group 0;" ::: "memory")

__device__ __forceinline__ void ldsm4(uint32_t* r, uint32_t a) {
    asm volatile("ldmatrix.sync.aligned.m8n8.x4.shared.b16 {%0,%1,%2,%3}, [%4];"
                 : "=r"(r[0]), "=r"(r[1]), "=r"(r[2]), "=r"(r[3]) : "r"(a));
}
__device__ __forceinline__ void ldsm4t(uint32_t* r, uint32_t a) {
    asm volatile("ldmatrix.sync.aligned.m8n8.x4.trans.shared.b16 {%0,%1,%2,%3}, [%4];"
                 : "=r"(r[0]), "=r"(r[1]), "=r"(r[2]), "=r"(r[3]) : "r"(a));
}
__device__ __forceinline__ void mma_fp(float* c, const uint32_t* a, const uint32_t* b) {
    asm volatile("mma.sync.aligned.m16n8k16.row.col.f32.f16.f16.f32 "
                 "{%0,%1,%2,%3}, {%4,%5,%6,%7}, {%8,%9}, {%0,%1,%2,%3};"
                 : "+f"(c[0]), "+f"(c[1]), "+f"(c[2]), "+f"(c[3])
                 : "r"(a[0]), "r"(a[1]), "r"(a[2]), "r"(a[3]), "r"(b[0]), "r"(b[1]));
}
__device__ __forceinline__ void stg_cs_f2(float* p, float2 v) {
    asm volatile("st.global.cs.v2.f32 [%0], {%1, %2};"
                 :: "l"(__cvta_generic_to_global(p)), "f"(v.x), "f"(v.y) : "memory");
}
__device__ __forceinline__ uint32_t h2exp2u(uint32_t x) {
    uint32_t r;
    asm("ex2.approx.f16x2 %0, %1;" : "=r"(r) : "r"(x));
    return r;
}

// ---------------------------------------------------------------------------
// fused prep: softmax_q | softmax_k | pack_mask | vhalf in one grid
// blocks: [0,128) q-softmax, [128,1152) k-softmax, [1152,1664) mask,
//         [1664,3712) v convert
// ---------------------------------------------------------------------------
__global__ void k_prep(const float* __restrict__ q, const float* __restrict__ k,
                       const float* __restrict__ v, const int* __restrict__ m) {
    __shared__ float red[32][8];
    int b = blockIdx.x;
    if (b < 128) {
        int nh = b >> 3, dchunk = b & 7;
        int dloc = threadIdx.x & 7, sy = threadIdx.x >> 3;
        int d = dchunk * 8 + dloc;
        const float* base = q + (size_t)nh * S * D + d;
        float sum = 0.f;
        for (int s = sy; s < S; s += 32) sum += __expf(base[(size_t)s * D]);
        red[sy][dloc] = sum;
        __syncthreads();
        for (int off = 16; off > 0; off >>= 1) {
            if (sy < off) red[sy][dloc] += red[sy + off][dloc];
            __syncthreads();
        }
        float iv = 1.f / red[0][dloc];
        __half* out = g_Qh + (size_t)nh * S * D + d;
        for (int s = sy; s < S; s += 32)
            out[(size_t)s * D] = __float2half_rn(__expf(base[(size_t)s * D]) * iv);
    } else if (b < 1152) {
        int idx = (b - 128) * 256 + threadIdx.x;
        if (idx >= NB * S * D) return;
        int n = idx / (S * D);
        int sd = idx - n * (S * D);
        const float* p = k + (size_t)n * HH * S * D + sd;
        __half* o = g_Kh + (size_t)n * HH * S * D + sd;
        float e[HH]; float sum = 0.f;
#pragma unroll
        for (int h = 0; h < HH; h++) { e[h] = __expf(p[(size_t)h * S * D]); sum += e[h]; }
        float iv = 1.f / sum;
#pragma unroll
        for (int h = 0; h < HH; h++) o[(size_t)h * S * D] = __float2half_rn(e[h] * iv);
    } else if (b < 1664) {
        int idx = (b - 1152) * 256 + threadIdx.x;
        if (idx >= S * SW) return;
        int qq = idx >> 6, w = idx & 63;
        const int* p = m + (size_t)qq * S + w * 32;
        unsigned bits = 0;
#pragma unroll
        for (int bb = 0; bb < 32; bb++) if (p[bb] != 0) bits |= (1u << bb);
        g_mb[idx] = bits;
    } else {
        int idx = (b - 1664) * 256 + threadIdx.x;
        if (idx >= NB * HH * S * D / 4) return;
        float4 f = *(const float4*)(v + (size_t)idx * 4);
        __half2 h01 = __floats2half2_rn(f.x, f.y);
        __half2 h23 = __floats2half2_rn(f.z, f.w);
        *(uint2*)(g_Vf + (size_t)idx * 4) = make_uint2(*(uint32_t*)&h01, *(uint32_t*)&h23);
    }
}

// ---------------------------------------------------------------------------
// smem layouts
// ---------------------------------------------------------------------------
#define O_INVL 0        /* invl (pass2) or srs (rowsum): 512 B */
#define O_MB0  512
#define O_MB1  2560
#define O_KB0  4608
#define O_KB1  20992    /* also Q staging during prologue */
#define RS_SMEM 37376
#define O_VH0  37376
#define O_VH1  53760
#define P2_SMEM 70144

// ---------------------------------------------------------------------------
// k_rowsum: GEMM1 with 2D warp tiling (4 M x 2 N), masked f16x2-exp, row sums
// ---------------------------------------------------------------------------
__global__ void __launch_bounds__(256, 2) k_rowsum() {
    extern __shared__ char smem[];
    const int tid = threadIdx.x, wid = tid >> 5, lid = tid & 31;
    const int g = lid >> 2, t = lid & 3;
    const int nw = wid & 1, mw = wid >> 1;      // 2 col-halves x 4 row-tiles
    const int nh = blockIdx.y, q0 = blockIdx.x * 128;
    const uint32_t sb = smem_u32(smem);
    float* srs = (float*)(smem + O_INVL);

    const __half* Qg = g_Qh + ((size_t)nh * S + q0) * D;
    const __half* Kg = g_Kh + (size_t)nh * S * D;

    // prefetch K tile 0 + mask 0
#pragma unroll
    for (int i = 0; i < 4; i++) {
        int idx = i * 256 + tid;
        int r = idx >> 3, s16 = idx & 7;
        cpa16(sb + O_KB0 + SWZ(r * 128 + s16 * 16), Kg + (size_t)r * 64 + s16 * 8);
    }
    if (tid < 128)
        cpa16(sb + O_MB0 + tid * 16, g_mb + (size_t)(q0 + tid) * SW);
    CPA_COMMIT();

    if (tid < 128) srs[tid] = 0.f;

    // stage Q in KB1, hoist 2 m-frags x 4 k-steps, recycle
#pragma unroll
    for (int i = 0; i < 4; i++) {
        int idx = i * 256 + tid;
        int r = idx >> 3, s16 = idx & 7;
        *(uint4*)(smem + O_KB1 + SWZ(r * 128 + s16 * 16)) =
            *(const uint4*)(Qg + (size_t)r * 64 + s16 * 8);
    }
    __syncthreads();
    uint32_t aQ[2][4][4];
#pragma unroll
    for (int m2 = 0; m2 < 2; m2++)
#pragma unroll
        for (int kk = 0; kk < 4; kk++) {
            int rl = 32 * mw + 16 * m2 + (lid & 7) + (lid & 8);
            int c16 = kk * 2 + (lid >> 4);
            ldsm4(aQ[m2][kk], sb + O_KB1 + SWZ(rl * 128 + c16 * 16));
        }
    __syncthreads();

    float rs[4] = {0.f, 0.f, 0.f, 0.f};   // rows 32mw + 16m2 + 8h + g

    for (int kt = 0; kt < 16; kt++) {
        CPA_WAIT0();
        __syncthreads();
        if (kt < 15) {
            int b = (kt + 1) & 1;
            uint32_t kb = b ? O_KB1 : O_KB0, mb = b ? O_MB1 : O_MB0;
#pragma unroll
            for (int i = 0; i < 4; i++) {
                int idx = i * 256 + tid;
                int r = idx >> 3, s16 = idx & 7;
                cpa16(sb + kb + SWZ(r * 128 + s16 * 16),
                      Kg + (size_t)((kt + 1) * 128 + r) * 64 + s16 * 8);
            }
            if (tid < 128)
                cpa16(sb + mb + tid * 16, g_mb + (size_t)(q0 + tid) * SW + (kt + 1) * 4);
            CPA_COMMIT();
        }
        const uint32_t kb = (kt & 1) ? O_KB1 : O_KB0;
        const uint32_t mb = (kt & 1) ? O_MB1 : O_MB0;

        // 8 n-frags for this warp's 64-col half, flat loop with lookahead
        float acc[2][4][4];
        uint32_t bn[8], bc[8];
        {
            int F = 8 * nw;
            ldsm4(bn,     sb + kb + SWZ((F * 8 + (lid & 7)) * 128 + (0 * 4 + (lid >> 3)) * 16));
            ldsm4(bn + 4, sb + kb + SWZ((F * 8 + (lid & 7)) * 128 + (1 * 4 + (lid >> 3)) * 16));
        }
#pragma unroll
        for (int s = 0; s < 8; s++) {
            const int nf = s & 3;
#pragma unroll
            for (int j = 0; j < 8; j++) bc[j] = bn[j];
            if (s < 7) {
                int F = 8 * nw + s + 1;
                ldsm4(bn,     sb + kb + SWZ((F * 8 + (lid & 7)) * 128 + (0 * 4 + (lid >> 3)) * 16));
                ldsm4(bn + 4, sb + kb + SWZ((F * 8 + (lid & 7)) * 128 + (1 * 4 + (lid >> 3)) * 16));
            }
#pragma unroll
            for (int m2 = 0; m2 < 2; m2++) {
                acc[m2][nf][0] = acc[m2][nf][1] = acc[m2][nf][2] = acc[m2][nf][3] = 0.f;
                mma_fp(acc[m2][nf], aQ[m2][0], bc);
                mma_fp(acc[m2][nf], aQ[m2][1], bc + 2);
                mma_fp(acc[m2][nf], aQ[m2][2], bc + 4);
                mma_fp(acc[m2][nf], aQ[m2][3], bc + 6);
            }
            if (nf == 3) {
                const int cc = s >> 2;
                const int w = 2 * nw + cc;           // 32-col word index
#pragma unroll
                for (int m2 = 0; m2 < 2; m2++) {
                    int r0 = 32 * mw + 16 * m2 + g;
                    unsigned w0 = *(unsigned*)(smem + mb + r0 * 16 + w * 4);
                    unsigned w1 = *(unsigned*)(smem + mb + (r0 + 8) * 16 + w * 4);
#pragma unroll
                    for (int u = 0; u < 4; u++) {
                        int bit = 8 * u + 2 * t;
                        __half2 x01 = __floats2half2_rn(acc[m2][u][0] * LOG2E, acc[m2][u][1] * LOG2E);
                        __half2 x23 = __floats2half2_rn(acc[m2][u][2] * LOG2E, acc[m2][u][3] * LOG2E);
                        uint32_t e01 = h2exp2u(*(uint32_t*)&x01);
                        uint32_t e23 = h2exp2u(*(uint32_t*)&x23);
                        float2 f01 = __half22float2(*(__half2*)&e01);
                        float2 f23 = __half22float2(*(__half2*)&e23);
                        if ((w0 >> bit) & 1)       rs[2 * m2]     += f01.x;
                        if ((w0 >> (bit + 1)) & 1) rs[2 * m2]     += f01.y;
                        if ((w1 >> bit) & 1)       rs[2 * m2 + 1] += f23.x;
                        if ((w1 >> (bit + 1)) & 1) rs[2 * m2 + 1] += f23.y;
                    }
                }
            }
        }
    }

    // reduce over t lanes, combine col-halves via smem atomics
#pragma unroll
    for (int rg = 0; rg < 4; rg++) {
        float v = rs[rg];
        v += __shfl_xor_sync(0xffffffffu, v, 1);
        v += __shfl_xor_sync(0xffffffffu, v, 2);
        if (t == 0) atomicAdd(&srs[32 * mw + 16 * (rg >> 1) + 8 * (rg & 1) + g], v);
    }
    __syncthreads();
    if (tid < 128) g_l[(size_t)nh * S + q0 + tid] = srs[tid];
}

// ---------------------------------------------------------------------------
// k_pass2: GEMM1 (pipelined), bias-matched f16x2 exp, normalize, stream attn,
// GEMM2 (pipelined V) -> ctx
// ---------------------------------------------------------------------------
__global__ void __launch_bounds__(256, 2) k_pass2(float* __restrict__ attn,
                                                  float* __restrict__ ctx) {
    extern __shared__ char smem[];
    const int tid = threadIdx.x, wid = tid >> 5, lid = tid & 31;
    const int g = lid >> 2, t = lid & 3;
    const int nh = blockIdx.y, q0 = blockIdx.x * 128;
    const uint32_t sb = smem_u32(smem);
    float* invl = (float*)(smem + O_INVL);

    const __half* Qg = g_Qh + ((size_t)nh * S + q0) * D;
    const __half* Kg = g_Kh + (size_t)nh * S * D;
    const __half* Vg = g_Vf + (size_t)nh * S * D;
    float* attnb = attn + (size_t)nh * S * S;

    // prefetch tile 0 (K, V, mask)
#pragma unroll
    for (int i = 0; i < 4; i++) {
        int idx = i * 256 + tid;
        int r = idx >> 3, s16 = idx & 7;
        uint32_t swo = SWZ(r * 128 + s16 * 16);
        size_t gofs = (size_t)r * 64 + s16 * 8;
        cpa16(sb + O_KB0 + swo, Kg + gofs);
        cpa16(sb + O_VH0 + swo, Vg + gofs);
    }
    if (tid < 128)
        cpa16(sb + O_MB0 + tid * 16, g_mb + (size_t)(q0 + tid) * SW);
    CPA_COMMIT();

    if (tid < 128) {
        float lv = g_l[(size_t)nh * S + q0 + tid];
        invl[tid] = (lv > 0.f) ? 1.f / lv : 0.f;
    }

    // stage Q in VH1 (overwritten only by kt=1 prefetch, after loop-top sync)
#pragma unroll
    for (int i = 0; i < 4; i++) {
        int idx = i * 256 + tid;
        int r = idx >> 3, s16 = idx & 7;
        *(uint4*)(smem + O_VH1 + SWZ(r * 128 + s16 * 16)) =
            *(const uint4*)(Qg + (size_t)r * 64 + s16 * 8);
    }
    __syncthreads();
    uint32_t aQ[4][4];
#pragma unroll
    for (int kk = 0; kk < 4; kk++) {
        int rl = 16 * wid + (lid & 7) + (lid & 8);
        int c16 = kk * 2 + (lid >> 4);
        ldsm4(aQ[kk], sb + O_VH1 + SWZ(rl * 128 + c16 * 16));
    }
    const int r0l = 16 * wid + g, r1l = r0l + 8;
    const float iv0 = invl[r0l], iv1 = invl[r1l];

    float ctxa[8][4];
#pragma unroll
    for (int n = 0; n < 8; n++) { ctxa[n][0] = ctxa[n][1] = ctxa[n][2] = ctxa[n][3] = 0.f; }

    for (int kt = 0; kt < 16; kt++) {
        CPA_WAIT0();
        __syncthreads();
        if (kt < 15) {
            int b = (kt + 1) & 1;
            uint32_t kb = b ? O_KB1 : O_KB0, vh = b ? O_VH1 : O_VH0;
            uint32_t mb = b ? O_MB1 : O_MB0;
#pragma unroll
            for (int i = 0; i < 4; i++) {
                int idx = i * 256 + tid;
                int r = idx >> 3, s16 = idx & 7;
                uint32_t swo = SWZ(r * 128 + s16 * 16);
                size_t gofs = (size_t)((kt + 1) * 128 + r) * 64 + s16 * 8;
                cpa16(sb + kb + swo, Kg + gofs);
                cpa16(sb + vh + swo, Vg + gofs);
            }
            if (tid < 128)
                cpa16(sb + mb + tid * 16, g_mb + (size_t)(q0 + tid) * SW + (kt + 1) * 4);
            CPA_COMMIT();
        }
        const int bsel = kt & 1;
        const uint32_t kb  = bsel ? O_KB1 : O_KB0;
        const uint32_t vhb = bsel ? O_VH1 : O_VH0;
        const uint32_t mb  = bsel ? O_MB1 : O_MB0;

        uint4 mw0 = *(uint4*)(smem + mb + r0l * 16);
        uint4 mw1 = *(uint4*)(smem + mb + r1l * 16);
        unsigned m0a[4] = {mw0.x, mw0.y, mw0.z, mw0.w};
        unsigned m1a[4] = {mw1.x, mw1.y, mw1.z, mw1.w};

#pragma unroll
        for (int c = 0; c < 4; c++) {
            // GEMM1 for 4 fragments (32 attn cols), pipelined B loads
            float acc4[4][4];
            uint32_t bn[8], bc[8];
            {
                int f = 4 * c;
                ldsm4(bn,     sb + kb + SWZ((f * 8 + (lid & 7)) * 128 + (0 * 4 + (lid >> 3)) * 16));
                ldsm4(bn + 4, sb + kb + SWZ((f * 8 + (lid & 7)) * 128 + (1 * 4 + (lid >> 3)) * 16));
            }
#pragma unroll
            for (int f4 = 0; f4 < 4; f4++) {
#pragma unroll
                for (int j = 0; j < 8; j++) bc[j] = bn[j];
                if (f4 < 3) {
                    int f = 4 * c + f4 + 1;
                    ldsm4(bn,     sb + kb + SWZ((f * 8 + (lid & 7)) * 128 + (0 * 4 + (lid >> 3)) * 16));
                    ldsm4(bn + 4, sb + kb + SWZ((f * 8 + (lid & 7)) * 128 + (1 * 4 + (lid >> 3)) * 16));
                }
                acc4[f4][0] = acc4[f4][1] = acc4[f4][2] = acc4[f4][3] = 0.f;
                mma_fp(acc4[f4], aQ[0], bc);
                mma_fp(acc4[f4], aQ[1], bc + 2);
                mma_fp(acc4[f4], aQ[2], bc + 4);
                mma_fp(acc4[f4], aQ[3], bc + 6);
            }
            // epilogue: f16x2 exp (bias-matched to rowsum), mask, normalize,
            // stream-store attn, pack W frags
            unsigned w0 = m0a[c], w1 = m1a[c];
            uint32_t wv[4][2];
#pragma unroll
            for (int f4 = 0; f4 < 4; f4++) {
                int bit = 8 * f4 + 2 * t;
                __half2 x01 = __floats2half2_rn(acc4[f4][0] * LOG2E, acc4[f4][1] * LOG2E);
                __half2 x23 = __floats2half2_rn(acc4[f4][2] * LOG2E, acc4[f4][3] * LOG2E);
                uint32_t eu01 = h2exp2u(*(uint32_t*)&x01);
                uint32_t eu23 = h2exp2u(*(uint32_t*)&x23);
                float2 f01 = __half22float2(*(__half2*)&eu01);
                float2 f23 = __half22float2(*(__half2*)&eu23);
                float e0 = ((w0 >> bit) & 1)       ? f01.x * iv0 : 0.f;
                float e1 = ((w0 >> (bit + 1)) & 1) ? f01.y * iv0 : 0.f;
                float e2 = ((w1 >> bit) & 1)       ? f23.x * iv1 : 0.f;
                float e3 = ((w1 >> (bit + 1)) & 1) ? f23.y * iv1 : 0.f;
                int col = kt * 128 + 32 * c + 8 * f4 + 2 * t;
                stg_cs_f2(&attnb[(size_t)(q0 + r0l) * S + col], make_float2(e0, e1));
                stg_cs_f2(&attnb[(size_t)(q0 + r1l) * S + col], make_float2(e2, e3));
                __half2 h01 = __floats2half2_rn(e0, e1);
                __half2 h23 = __floats2half2_rn(e2, e3);
                wv[f4][0] = *(uint32_t*)&h01;
                wv[f4][1] = *(uint32_t*)&h23;
            }
            // GEMM2 partial, pipelined V loads
            uint32_t aH0[4] = {wv[0][0], wv[0][1], wv[1][0], wv[1][1]};
            uint32_t aH1[4] = {wv[2][0], wv[2][1], wv[3][0], wv[3][1]};
            uint32_t bhn[4], bhc[4];
            ldsm4t(bhn, sb + vhb + SWZ((c * 32 + lid) * 128 + 0 * 16));
#pragma unroll
            for (int n8 = 0; n8 < 8; n8++) {
#pragma unroll
                for (int j = 0; j < 4; j++) bhc[j] = bhn[j];
                if (n8 < 7)
                    ldsm4t(bhn, sb + vhb + SWZ((c * 32 + lid) * 128 + (n8 + 1) * 16));
                mma_fp(ctxa[n8], aH0, bhc);
                mma_fp(ctxa[n8], aH1, bhc + 2);
            }
        }
    }

    // ctx store
#pragma unroll
    for (int n8 = 0; n8 < 8; n8++) {
        int c = 8 * n8 + 2 * t;
        stg_cs_f2(&ctx[((size_t)nh * S + q0 + r0l) * D + c], make_float2(ctxa[n8][0], ctxa[n8][1]));
        stg_cs_f2(&ctx[((size_t)nh * S + q0 + r1l) * D + c], make_float2(ctxa[n8][2], ctxa[n8][3]));
    }
}

// ---------------------------------------------------------------------------
extern "C" void kernel_launch(void* const* d_in, const int* in_sizes, int n_in,
                              void* d_out, int out_size) {
    const float* q = (const float*)d_in[0];
    const float* k = (const float*)d_in[1];
    const float* v = (const float*)d_in[2];
    const int*   m = (const int*)d_in[3];

    float* ctx  = (float*)d_out;
    float* attn = (float*)d_out + CTX_ELEMS;

    cudaFuncSetAttribute(k_rowsum, cudaFuncAttributeMaxDynamicSharedMemorySize, RS_SMEM);
    cudaFuncSetAttribute(k_pass2,  cudaFuncAttributeMaxDynamicSharedMemorySize, P2_SMEM);

    k_prep<<<3712, 256>>>(q, k, v, m);
    k_rowsum<<<dim3(16, NH), 256, RS_SMEM>>>();
    k_pass2<<<dim3(16, NH), 256, P2_SMEM>>>(attn, ctx);
}